// round 6
// baseline (speedup 1.0000x reference)
#include <cuda_runtime.h>
#include <math.h>
#include <stdint.h>

#define H1 128
#define H2 256
#define NCLS 16
#define MAXN 65536
#define MAXE 1048576

// ---- scratch (device globals: allocation-free per harness rules) ----
__device__ float g_y[MAXN * H1];        // relu(x @ Wp^T + bp)
__device__ float g_pooled[MAXN * H1];   // segment-max result
__device__ float g_h[MAXN * H1];        // combined hidden
__device__ float g_h2[MAXN * H2];       // MLP hidden
__device__ int   g_hist[MAXN];          // per-dst edge counts
__device__ int   g_offs[MAXN + 1];      // exclusive offsets
__device__ int   g_cursor[MAXN];        // scatter cursors
__device__ int   g_ssrc[MAXE];          // src ids bucketed by dst

enum { ACT_RELU = 1, ACT_LEAKY = 2 };

__device__ __forceinline__ uint32_t f2tf32(float v)
{
    uint32_t r;
    asm("cvt.rna.tf32.f32 %0, %1;" : "=r"(r) : "f"(v));
    return r;
}

__device__ __forceinline__ void mma_tf32(
    float* c, const uint32_t* a, const uint32_t* b)
{
    asm volatile(
        "mma.sync.aligned.m16n8k8.row.col.f32.tf32.tf32.f32 "
        "{%0,%1,%2,%3}, {%4,%5,%6,%7}, {%8,%9}, {%0,%1,%2,%3};\n"
        : "+f"(c[0]), "+f"(c[1]), "+f"(c[2]), "+f"(c[3])
        : "r"(a[0]), "r"(a[1]), "r"(a[2]), "r"(a[3]),
          "r"(b[0]), "r"(b[1]));
}

// ============================================================================
// TF32 tensor-core GEMM:
//   C[M,N] = act( A[M,K] @ B[N,K]^T (+ A2 @ B2^T) + bias[N] )
// BM=BN=128, BK=32. 256 threads = 8 warps (2 M x 4 N), 64x32 per warp.
// Requires M%128==0, N%128==0, K%32==0.
// ============================================================================
template <int ACT, bool DUAL>
__global__ void __launch_bounds__(256) gemm_tc(
    const float* __restrict__ A, const float* __restrict__ B,
    const float* __restrict__ A2, const float* __restrict__ B2,
    const float* __restrict__ bias, float* __restrict__ C,
    int M, int N, int K)
{
    const int BM = 128, BN = 128, BK = 32, LDA = BK + 4;
    __shared__ uint32_t As[BM * LDA];
    __shared__ uint32_t Bs[BN * LDA];

    const int tid  = threadIdx.x;
    const int lane = tid & 31;
    const int warp = tid >> 5;
    const int wm = (warp & 1) * 64;      // warp M offset in tile
    const int wn = (warp >> 1) * 32;     // warp N offset in tile
    const int g  = lane >> 2;            // groupID (0..7)
    const int tg = lane & 3;             // thread-in-group (0..3)
    const int m0 = blockIdx.y * BM;
    const int n0 = blockIdx.x * BN;

    float acc[4][4][4];                  // [mi][ni][frag]
    #pragma unroll
    for (int mi = 0; mi < 4; mi++)
        #pragma unroll
        for (int ni = 0; ni < 4; ni++)
            #pragma unroll
            for (int c = 0; c < 4; c++) acc[mi][ni][c] = 0.0f;

    const int nPass = DUAL ? 2 : 1;
    for (int pass = 0; pass < nPass; ++pass) {
        const float* Ap = (DUAL && pass) ? A2 : A;
        const float* Bp = (DUAL && pass) ? B2 : B;
        for (int k0 = 0; k0 < K; k0 += BK) {
            // stage 128x32 A and B tiles, converting to tf32
            #pragma unroll
            for (int i = 0; i < 4; i++) {
                int fi = i * 256 + tid;          // 0..1023 float4 slots
                int r  = fi >> 3;                // row 0..127
                int c4 = (fi & 7) * 4;           // col 0,4,..,28
                float4 va = *reinterpret_cast<const float4*>(
                    Ap + (size_t)(m0 + r) * K + k0 + c4);
                As[r * LDA + c4 + 0] = f2tf32(va.x);
                As[r * LDA + c4 + 1] = f2tf32(va.y);
                As[r * LDA + c4 + 2] = f2tf32(va.z);
                As[r * LDA + c4 + 3] = f2tf32(va.w);
                float4 vb = *reinterpret_cast<const float4*>(
                    Bp + (size_t)(n0 + r) * K + k0 + c4);
                Bs[r * LDA + c4 + 0] = f2tf32(vb.x);
                Bs[r * LDA + c4 + 1] = f2tf32(vb.y);
                Bs[r * LDA + c4 + 2] = f2tf32(vb.z);
                Bs[r * LDA + c4 + 3] = f2tf32(vb.w);
            }
            __syncthreads();

            #pragma unroll
            for (int ks = 0; ks < 4; ks++) {
                const int kk = ks * 8;
                uint32_t af[4][4];
                #pragma unroll
                for (int mi = 0; mi < 4; mi++) {
                    int rb = wm + mi * 16 + g;
                    af[mi][0] = As[rb * LDA + kk + tg];
                    af[mi][1] = As[(rb + 8) * LDA + kk + tg];
                    af[mi][2] = As[rb * LDA + kk + tg + 4];
                    af[mi][3] = As[(rb + 8) * LDA + kk + tg + 4];
                }
                uint32_t bf[4][2];
                #pragma unroll
                for (int ni = 0; ni < 4; ni++) {
                    int nb = wn + ni * 8 + g;
                    bf[ni][0] = Bs[nb * LDA + kk + tg];
                    bf[ni][1] = Bs[nb * LDA + kk + tg + 4];
                }
                #pragma unroll
                for (int mi = 0; mi < 4; mi++)
                    #pragma unroll
                    for (int ni = 0; ni < 4; ni++)
                        mma_tf32(acc[mi][ni], af[mi], bf[ni]);
            }
            __syncthreads();
        }
    }

    // epilogue: bias + activation, float2 stores
    #pragma unroll
    for (int mi = 0; mi < 4; mi++) {
        const int r0 = m0 + wm + mi * 16 + g;
        #pragma unroll
        for (int ni = 0; ni < 4; ni++) {
            const int col = n0 + wn + ni * 8 + tg * 2;
            const float b0 = bias[col], b1 = bias[col + 1];
            float v0 = acc[mi][ni][0] + b0;
            float v1 = acc[mi][ni][1] + b1;
            float v2 = acc[mi][ni][2] + b0;
            float v3 = acc[mi][ni][3] + b1;
            if (ACT == ACT_RELU) {
                v0 = fmaxf(v0, 0.f); v1 = fmaxf(v1, 0.f);
                v2 = fmaxf(v2, 0.f); v3 = fmaxf(v3, 0.f);
            }
            if (ACT == ACT_LEAKY) {
                v0 = (v0 > 0.f) ? v0 : 0.01f * v0;
                v1 = (v1 > 0.f) ? v1 : 0.01f * v1;
                v2 = (v2 > 0.f) ? v2 : 0.01f * v2;
                v3 = (v3 > 0.f) ? v3 : 0.01f * v3;
            }
            *reinterpret_cast<float2*>(C + (size_t)r0 * N + col) =
                make_float2(v0, v1);
            *reinterpret_cast<float2*>(C + (size_t)(r0 + 8) * N + col) =
                make_float2(v2, v3);
        }
    }
}

// ============================================================================
// Edge bucketing (counting sort by dst) + segmented max
// ============================================================================
__global__ void zero_hist(int* __restrict__ hist, int n)
{
    int i = blockIdx.x * blockDim.x + threadIdx.x;
    if (i < n) hist[i] = 0;
}

__global__ void hist_kernel(const int* __restrict__ dst, int* __restrict__ hist, int E)
{
    int i = blockIdx.x * blockDim.x + threadIdx.x;
    if (i < E) atomicAdd(&hist[dst[i]], 1);
}

// one block, 1024 threads, 64 nodes each: exclusive scan of hist into offs/cursor
__global__ void __launch_bounds__(1024) scan_kernel(
    const int* __restrict__ hist, int* __restrict__ offs,
    int* __restrict__ cursor, int N)
{
    __shared__ int part[1024];
    const int tid = threadIdx.x;
    const int per = N / 1024;
    const int base = tid * per;
    int s = 0;
    for (int i = 0; i < per; i++) s += hist[base + i];
    part[tid] = s;
    __syncthreads();
    for (int d = 1; d < 1024; d <<= 1) {
        int v = (tid >= d) ? part[tid - d] : 0;
        __syncthreads();
        part[tid] += v;
        __syncthreads();
    }
    int run = (tid == 0) ? 0 : part[tid - 1];
    for (int i = 0; i < per; i++) {
        offs[base + i] = run;
        cursor[base + i] = run;
        run += hist[base + i];
    }
    if (tid == 1023) offs[N] = run;
}

__global__ void scatter_edges(const int* __restrict__ src, const int* __restrict__ dst,
                              int* __restrict__ cursor, int* __restrict__ ssrc, int E)
{
    int i = blockIdx.x * blockDim.x + threadIdx.x;
    if (i < E) {
        int p = atomicAdd(&cursor[dst[i]], 1);
        ssrc[p] = src[i];
    }
}

// one warp per node: pooled[n] = max over bucketed edges of y[src] (0 if none)
__global__ void __launch_bounds__(256) pool_max(
    const float* __restrict__ y, const int* __restrict__ offs,
    const int* __restrict__ ssrc, float* __restrict__ pooled, int N)
{
    int w = (blockIdx.x * blockDim.x + threadIdx.x) >> 5;
    int lane = threadIdx.x & 31;
    if (w >= N) return;
    int e = offs[w], end = offs[w + 1];
    float4 m = make_float4(0.f, 0.f, 0.f, 0.f);
    for (; e + 3 < end; e += 4) {
        int s0 = ssrc[e], s1 = ssrc[e + 1], s2 = ssrc[e + 2], s3 = ssrc[e + 3];
        float4 v0 = *reinterpret_cast<const float4*>(y + (size_t)s0 * H1 + lane * 4);
        float4 v1 = *reinterpret_cast<const float4*>(y + (size_t)s1 * H1 + lane * 4);
        float4 v2 = *reinterpret_cast<const float4*>(y + (size_t)s2 * H1 + lane * 4);
        float4 v3 = *reinterpret_cast<const float4*>(y + (size_t)s3 * H1 + lane * 4);
        m.x = fmaxf(m.x, fmaxf(fmaxf(v0.x, v1.x), fmaxf(v2.x, v3.x)));
        m.y = fmaxf(m.y, fmaxf(fmaxf(v0.y, v1.y), fmaxf(v2.y, v3.y)));
        m.z = fmaxf(m.z, fmaxf(fmaxf(v0.z, v1.z), fmaxf(v2.z, v3.z)));
        m.w = fmaxf(m.w, fmaxf(fmaxf(v0.w, v1.w), fmaxf(v2.w, v3.w)));
    }
    for (; e < end; e++) {
        int s0 = ssrc[e];
        float4 v0 = *reinterpret_cast<const float4*>(y + (size_t)s0 * H1 + lane * 4);
        m.x = fmaxf(m.x, v0.x); m.y = fmaxf(m.y, v0.y);
        m.z = fmaxf(m.z, v0.z); m.w = fmaxf(m.w, v0.w);
    }
    *reinterpret_cast<float4*>(pooled + (size_t)w * H1 + lane * 4) = m;
}

// ============================================================================
// Head: out[M,16] = sigmoid(h2[M,256] @ W2[16,256]^T + b2), 16 rows/block
// ============================================================================
__global__ void __launch_bounds__(256) head_kernel(
    const float* __restrict__ h2, const float* __restrict__ W2,
    const float* __restrict__ b2, float* __restrict__ out, int M)
{
    __shared__ float ws[NCLS][H2 + 1];
    __shared__ float hs[16][H2 + 1];
    const int tid = threadIdx.x;
    const int m0 = blockIdx.x * 16;

    for (int i = tid; i < NCLS * H2; i += 256)
        ws[i / H2][i % H2] = W2[i];
    for (int i = tid; i < 16 * H2; i += 256)
        hs[i / H2][i % H2] = h2[(size_t)m0 * H2 + i];
    __syncthreads();

    const int r = tid >> 4;
    const int c = tid & 15;
    float acc = 0.0f;
    #pragma unroll 8
    for (int k = 0; k < H2; k++) acc += hs[r][k] * ws[c][k];
    acc += b2[c];
    out[(size_t)(m0 + r) * NCLS + c] = 1.0f / (1.0f + expf(-acc));
}

extern "C" void kernel_launch(void* const* d_in, const int* in_sizes, int n_in,
                              void* d_out, int out_size)
{
    const float* x  = (const float*)d_in[0];
    const float* Wp = (const float*)d_in[1];
    const float* bp = (const float*)d_in[2];
    const float* Ws = (const float*)d_in[3];
    const float* Wn = (const float*)d_in[4];
    const float* bn = (const float*)d_in[5];
    const float* W1 = (const float*)d_in[6];
    const float* b1 = (const float*)d_in[7];
    const float* W2 = (const float*)d_in[8];
    const float* b2 = (const float*)d_in[9];
    const int* src  = (const int*)d_in[10];
    const int* dst  = (const int*)d_in[11];
    float* out = (float*)d_out;

    const int M = in_sizes[0] / H1;   // IN_FEATS == H1 == 128
    const int E = in_sizes[10];

    float *y, *pooled, *h, *h2;
    int *hist, *offs, *cursor, *ssrc;
    cudaGetSymbolAddress((void**)&y, g_y);
    cudaGetSymbolAddress((void**)&pooled, g_pooled);
    cudaGetSymbolAddress((void**)&h, g_h);
    cudaGetSymbolAddress((void**)&h2, g_h2);
    cudaGetSymbolAddress((void**)&hist, g_hist);
    cudaGetSymbolAddress((void**)&offs, g_offs);
    cudaGetSymbolAddress((void**)&cursor, g_cursor);
    cudaGetSymbolAddress((void**)&ssrc, g_ssrc);

    // --- edge bucketing ---
    zero_hist<<<(M + 255) / 256, 256>>>(hist, M);
    hist_kernel<<<(E + 255) / 256, 256>>>(dst, hist, E);
    scan_kernel<<<1, 1024>>>(hist, offs, cursor, M);
    scatter_edges<<<(E + 255) / 256, 256>>>(src, dst, cursor, ssrc, E);

    // --- y = relu(x @ Wp^T + bp)  [M,128] ---
    dim3 g1(H1 / 128, M / 128);
    gemm_tc<ACT_RELU, false><<<g1, 256>>>(x, Wp, nullptr, nullptr, bp, y,
                                          M, H1, H1);

    // --- pooled[n] = segmented max of y over incoming edges ---
    pool_max<<<(M + 7) / 8, 256>>>(y, offs, ssrc, pooled, M);

    // --- h = leaky(x @ Ws^T + pooled @ Wn^T + bn)  [M,128] ---
    gemm_tc<ACT_LEAKY, true><<<g1, 256>>>(x, Ws, pooled, Wn, bn, h,
                                          M, H1, H1);

    // --- h2 = leaky(h @ W1^T + b1)  [M,256] ---
    dim3 g2(H2 / 128, M / 128);
    gemm_tc<ACT_LEAKY, false><<<g2, 256>>>(h, W1, nullptr, nullptr, b1, h2,
                                           M, H2, H1);

    // --- out = sigmoid(h2 @ W2^T + b2)  [M,16] ---
    head_kernel<<<M / 16, 256>>>(h2, W2, b2, out, M);
}

// round 7
// speedup vs baseline: 1.7584x; 1.7584x over previous
#include <cuda_runtime.h>
#include <cuda_fp16.h>
#include <math.h>
#include <stdint.h>

#define H1 128
#define H2 256
#define NCLS 16
#define MAXN 65536
#define MAXE 1048576

// ---- scratch (device globals: allocation-free per harness rules) ----
__device__ __align__(16) __half g_y[MAXN * H1];       // relu(x@Wp^T+bp), fp16
__device__ __align__(16) __half g_pooled[MAXN * H1];  // segment-max, fp16
__device__ __align__(16) __half g_h[MAXN * H1];       // combined hidden, fp16
__device__ __align__(16) __half g_h2[MAXN * H2];      // MLP hidden, fp16
__device__ int g_hist[MAXN];
__device__ int g_offs[MAXN + 1];
__device__ int g_cursor[MAXN];
__device__ int g_ssrc[MAXE];

enum { ACT_RELU = 1, ACT_LEAKY = 2 };

__device__ __forceinline__ void mma_f16(
    float* c, const uint32_t* a, const uint32_t* b)
{
    asm volatile(
        "mma.sync.aligned.m16n8k16.row.col.f32.f16.f16.f32 "
        "{%0,%1,%2,%3}, {%4,%5,%6,%7}, {%8,%9}, {%0,%1,%2,%3};\n"
        : "+f"(c[0]), "+f"(c[1]), "+f"(c[2]), "+f"(c[3])
        : "r"(a[0]), "r"(a[1]), "r"(a[2]), "r"(a[3]),
          "r"(b[0]), "r"(b[1]));
}

__device__ __forceinline__ void ldsm_x4(
    uint32_t& r0, uint32_t& r1, uint32_t& r2, uint32_t& r3, uint32_t addr)
{
    asm volatile(
        "ldmatrix.sync.aligned.m8n8.x4.shared.b16 {%0,%1,%2,%3}, [%4];"
        : "=r"(r0), "=r"(r1), "=r"(r2), "=r"(r3) : "r"(addr));
}

// ============================================================================
// fp16 tensor-core GEMM:
//   C[M,N](fp16) = act( A[M,K] @ B[N,K]^T (+ A1 @ B1^T) + bias[N] )
// A operands fp32 or fp16 (template), B operands fp32 (weights).
// BM=BN=128, BK=64, 256 threads = 8 warps (2M x 4N), 64x32 per warp.
// Requires M%128==0, N%128==0, K%64==0.
// ============================================================================
template <int ACT, int NPASS, bool A0H, bool A1H>
__global__ void __launch_bounds__(256) gemm_h(
    const void* __restrict__ A0, const float* __restrict__ B0,
    const void* __restrict__ A1, const float* __restrict__ B1,
    const float* __restrict__ bias, __half* __restrict__ C,
    int M, int N, int K)
{
    const int BK = 64, LDS_ = 72;                 // halfs per smem row (64+8 pad)
    __shared__ __half As[128 * LDS_];
    __shared__ __half Bs[128 * LDS_];

    const int tid  = threadIdx.x;
    const int lane = tid & 31;
    const int warp = tid >> 5;
    const int wm = (warp & 1) * 64;
    const int wn = (warp >> 1) * 32;
    const int m0 = blockIdx.y * 128;
    const int n0 = blockIdx.x * 128;
    const int g  = lane >> 2;
    const int tg = lane & 3;

    const uint32_t as_base = (uint32_t)__cvta_generic_to_shared(As);
    const uint32_t bs_base = (uint32_t)__cvta_generic_to_shared(Bs);
    // ldmatrix per-lane offsets (in half units)
    const int a_off = (wm + (lane & 15)) * LDS_ + (lane >> 4) * 8;
    const int b_off = (wn + ((lane >> 4) & 1) * 8 + (lane & 7)) * LDS_
                    + ((lane >> 3) & 1) * 8;

    float acc[4][4][4];
    #pragma unroll
    for (int mi = 0; mi < 4; mi++)
        #pragma unroll
        for (int ni = 0; ni < 4; ni++)
            #pragma unroll
            for (int c = 0; c < 4; c++) acc[mi][ni][c] = 0.0f;

    #pragma unroll
    for (int pass = 0; pass < NPASS; ++pass) {
        const bool AH = pass ? A1H : A0H;
        const void*  Ap = pass ? A1 : A0;
        const float* Bp = pass ? B1 : B0;
        for (int k0 = 0; k0 < K; k0 += BK) {
            // ---- stage A tile (128 x 64 halfs) ----
            if (AH) {
                const __half* Ah = (const __half*)Ap;
                #pragma unroll
                for (int it = 0; it < 4; it++) {
                    int f = it * 256 + tid;       // uint4 chunk: 8 halfs
                    int r = f >> 3, c8 = (f & 7) * 8;
                    uint4 v = *reinterpret_cast<const uint4*>(
                        Ah + (size_t)(m0 + r) * K + k0 + c8);
                    *reinterpret_cast<uint4*>(&As[r * LDS_ + c8]) = v;
                }
            } else {
                const float* Af = (const float*)Ap;
                #pragma unroll
                for (int it = 0; it < 8; it++) {
                    int f = it * 256 + tid;       // float4 chunk
                    int r = f >> 4, c4 = (f & 15) * 4;
                    float4 v = *reinterpret_cast<const float4*>(
                        Af + (size_t)(m0 + r) * K + k0 + c4);
                    __half2 h01 = __floats2half2_rn(v.x, v.y);
                    __half2 h23 = __floats2half2_rn(v.z, v.w);
                    *reinterpret_cast<__half2*>(&As[r * LDS_ + c4]) = h01;
                    *reinterpret_cast<__half2*>(&As[r * LDS_ + c4 + 2]) = h23;
                }
            }
            // ---- stage B tile (128 x 64 halfs), fp32 weights ----
            #pragma unroll
            for (int it = 0; it < 8; it++) {
                int f = it * 256 + tid;
                int r = f >> 4, c4 = (f & 15) * 4;
                float4 v = *reinterpret_cast<const float4*>(
                    Bp + (size_t)(n0 + r) * K + k0 + c4);
                __half2 h01 = __floats2half2_rn(v.x, v.y);
                __half2 h23 = __floats2half2_rn(v.z, v.w);
                *reinterpret_cast<__half2*>(&Bs[r * LDS_ + c4]) = h01;
                *reinterpret_cast<__half2*>(&Bs[r * LDS_ + c4 + 2]) = h23;
            }
            __syncthreads();

            // ---- compute: 4 k-steps of 16 ----
            #pragma unroll
            for (int ks = 0; ks < 4; ks++) {
                const int kk = ks * 16;
                uint32_t af[4][4];
                #pragma unroll
                for (int mi = 0; mi < 4; mi++)
                    ldsm_x4(af[mi][0], af[mi][1], af[mi][2], af[mi][3],
                            as_base + (uint32_t)(a_off + mi * 16 * LDS_ + kk) * 2);
                uint32_t bf[4][2];
                #pragma unroll
                for (int nip = 0; nip < 2; nip++) {
                    uint32_t r0, r1, r2, r3;
                    ldsm_x4(r0, r1, r2, r3,
                            bs_base + (uint32_t)(b_off + nip * 16 * LDS_ + kk) * 2);
                    bf[2 * nip][0] = r0;     bf[2 * nip][1] = r1;
                    bf[2 * nip + 1][0] = r2; bf[2 * nip + 1][1] = r3;
                }
                #pragma unroll
                for (int mi = 0; mi < 4; mi++)
                    #pragma unroll
                    for (int ni = 0; ni < 4; ni++)
                        mma_f16(acc[mi][ni], af[mi], bf[ni]);
            }
            __syncthreads();
        }
    }

    // ---- epilogue: bias + activation, half2 stores ----
    #pragma unroll
    for (int mi = 0; mi < 4; mi++) {
        const int r0 = m0 + wm + mi * 16 + g;
        #pragma unroll
        for (int ni = 0; ni < 4; ni++) {
            const int col = n0 + wn + ni * 8 + tg * 2;
            const float b0 = bias[col], b1 = bias[col + 1];
            float v0 = acc[mi][ni][0] + b0;
            float v1 = acc[mi][ni][1] + b1;
            float v2 = acc[mi][ni][2] + b0;
            float v3 = acc[mi][ni][3] + b1;
            if (ACT == ACT_RELU) {
                v0 = fmaxf(v0, 0.f); v1 = fmaxf(v1, 0.f);
                v2 = fmaxf(v2, 0.f); v3 = fmaxf(v3, 0.f);
            }
            if (ACT == ACT_LEAKY) {
                v0 = (v0 > 0.f) ? v0 : 0.01f * v0;
                v1 = (v1 > 0.f) ? v1 : 0.01f * v1;
                v2 = (v2 > 0.f) ? v2 : 0.01f * v2;
                v3 = (v3 > 0.f) ? v3 : 0.01f * v3;
            }
            *reinterpret_cast<__half2*>(C + (size_t)r0 * N + col) =
                __floats2half2_rn(v0, v1);
            *reinterpret_cast<__half2*>(C + (size_t)(r0 + 8) * N + col) =
                __floats2half2_rn(v2, v3);
        }
    }
}

// ============================================================================
// Edge bucketing (counting sort by dst) + segmented max (fp16)
// ============================================================================
__global__ void zero_hist(int* __restrict__ hist, int n)
{
    int i = blockIdx.x * blockDim.x + threadIdx.x;
    if (i < n) hist[i] = 0;
}

__global__ void hist_kernel(const int* __restrict__ dst, int* __restrict__ hist, int E)
{
    int i = blockIdx.x * blockDim.x + threadIdx.x;
    if (i < E) atomicAdd(&hist[dst[i]], 1);
}

__global__ void __launch_bounds__(1024) scan_kernel(
    const int* __restrict__ hist, int* __restrict__ offs,
    int* __restrict__ cursor, int N)
{
    __shared__ int part[1024];
    const int tid = threadIdx.x;
    const int per = N / 1024;
    const int base = tid * per;
    int s = 0;
    for (int i = 0; i < per; i++) s += hist[base + i];
    part[tid] = s;
    __syncthreads();
    for (int d = 1; d < 1024; d <<= 1) {
        int v = (tid >= d) ? part[tid - d] : 0;
        __syncthreads();
        part[tid] += v;
        __syncthreads();
    }
    int run = (tid == 0) ? 0 : part[tid - 1];
    for (int i = 0; i < per; i++) {
        offs[base + i] = run;
        cursor[base + i] = run;
        run += hist[base + i];
    }
    if (tid == 1023) offs[N] = run;
}

__global__ void scatter_edges(const int* __restrict__ src, const int* __restrict__ dst,
                              int* __restrict__ cursor, int* __restrict__ ssrc, int E)
{
    int i = blockIdx.x * blockDim.x + threadIdx.x;
    if (i < E) {
        int p = atomicAdd(&cursor[dst[i]], 1);
        ssrc[p] = src[i];
    }
}

// one warp per node; y rows are 128 halfs = 32 uint2 chunks, one per lane
__global__ void __launch_bounds__(256) pool_max(
    const uint2* __restrict__ y, const int* __restrict__ offs,
    const int* __restrict__ ssrc, uint2* __restrict__ pooled, int N)
{
    int w = (blockIdx.x * blockDim.x + threadIdx.x) >> 5;
    int lane = threadIdx.x & 31;
    if (w >= N) return;
    int e = offs[w], end = offs[w + 1];
    __half2 m0 = __float2half2_rn(0.f);
    __half2 m1 = m0;
    for (; e + 3 < end; e += 4) {
        int s0 = ssrc[e], s1 = ssrc[e + 1], s2 = ssrc[e + 2], s3 = ssrc[e + 3];
        uint2 v0 = y[(size_t)s0 * 32 + lane];
        uint2 v1 = y[(size_t)s1 * 32 + lane];
        uint2 v2 = y[(size_t)s2 * 32 + lane];
        uint2 v3 = y[(size_t)s3 * 32 + lane];
        m0 = __hmax2(m0, __hmax2(__hmax2(*(__half2*)&v0.x, *(__half2*)&v1.x),
                                 __hmax2(*(__half2*)&v2.x, *(__half2*)&v3.x)));
        m1 = __hmax2(m1, __hmax2(__hmax2(*(__half2*)&v0.y, *(__half2*)&v1.y),
                                 __hmax2(*(__half2*)&v2.y, *(__half2*)&v3.y)));
    }
    for (; e < end; e++) {
        uint2 v0 = y[(size_t)ssrc[e] * 32 + lane];
        m0 = __hmax2(m0, *(__half2*)&v0.x);
        m1 = __hmax2(m1, *(__half2*)&v0.y);
    }
    uint2 o;
    o.x = *(uint32_t*)&m0;
    o.y = *(uint32_t*)&m1;
    pooled[(size_t)w * 32 + lane] = o;
}

// ============================================================================
// Head: out[M,16] = sigmoid(h2[M,256](fp16) @ W2[16,256]^T + b2), 16 rows/block
// ============================================================================
__global__ void __launch_bounds__(256) head_kernel(
    const __half* __restrict__ h2, const float* __restrict__ W2,
    const float* __restrict__ b2, float* __restrict__ out, int M)
{
    __shared__ float ws[NCLS][H2 + 1];
    __shared__ float hs[16][H2 + 1];
    const int tid = threadIdx.x;
    const int m0 = blockIdx.x * 16;

    for (int i = tid; i < NCLS * H2; i += 256)
        ws[i / H2][i % H2] = W2[i];
    for (int i = tid; i < 16 * H2; i += 256)
        hs[i / H2][i % H2] = __half2float(h2[(size_t)m0 * H2 + i]);
    __syncthreads();

    const int r = tid >> 4;
    const int c = tid & 15;
    float acc = 0.0f;
    #pragma unroll 8
    for (int k = 0; k < H2; k++) acc += hs[r][k] * ws[c][k];
    acc += b2[c];
    out[(size_t)(m0 + r) * NCLS + c] = 1.0f / (1.0f + expf(-acc));
}

extern "C" void kernel_launch(void* const* d_in, const int* in_sizes, int n_in,
                              void* d_out, int out_size)
{
    const float* x  = (const float*)d_in[0];
    const float* Wp = (const float*)d_in[1];
    const float* bp = (const float*)d_in[2];
    const float* Ws = (const float*)d_in[3];
    const float* Wn = (const float*)d_in[4];
    const float* bn = (const float*)d_in[5];
    const float* W1 = (const float*)d_in[6];
    const float* b1 = (const float*)d_in[7];
    const float* W2 = (const float*)d_in[8];
    const float* b2 = (const float*)d_in[9];
    const int* src  = (const int*)d_in[10];
    const int* dst  = (const int*)d_in[11];
    float* out = (float*)d_out;

    const int M = in_sizes[0] / H1;   // IN_FEATS == H1 == 128
    const int E = in_sizes[10];

    __half *y, *pooled, *h, *h2;
    int *hist, *offs, *cursor, *ssrc;
    cudaGetSymbolAddress((void**)&y, g_y);
    cudaGetSymbolAddress((void**)&pooled, g_pooled);
    cudaGetSymbolAddress((void**)&h, g_h);
    cudaGetSymbolAddress((void**)&h2, g_h2);
    cudaGetSymbolAddress((void**)&hist, g_hist);
    cudaGetSymbolAddress((void**)&offs, g_offs);
    cudaGetSymbolAddress((void**)&cursor, g_cursor);
    cudaGetSymbolAddress((void**)&ssrc, g_ssrc);

    // --- edge bucketing ---
    zero_hist<<<(M + 255) / 256, 256>>>(hist, M);
    hist_kernel<<<(E + 255) / 256, 256>>>(dst, hist, E);
    scan_kernel<<<1, 1024>>>(hist, offs, cursor, M);
    scatter_edges<<<(E + 255) / 256, 256>>>(src, dst, cursor, ssrc, E);

    // --- y = relu(x @ Wp^T + bp)  [M,128] fp16 ---
    dim3 g1(1, M / 128);
    gemm_h<ACT_RELU, 1, false, false><<<g1, 256>>>(
        x, Wp, nullptr, nullptr, bp, y, M, H1, H1);

    // --- pooled[n] = segmented max of y over incoming edges ---
    pool_max<<<(M + 7) / 8, 256>>>((const uint2*)y, offs, ssrc,
                                   (uint2*)pooled, M);

    // --- h = leaky(x @ Ws^T + pooled @ Wn^T + bn)  [M,128] fp16 ---
    gemm_h<ACT_LEAKY, 2, false, true><<<g1, 256>>>(
        x, Ws, pooled, Wn, bn, h, M, H1, H1);

    // --- h2 = leaky(h @ W1^T + b1)  [M,256] fp16 ---
    dim3 g2(H2 / 128, M / 128);
    gemm_h<ACT_LEAKY, 1, true, false><<<g2, 256>>>(
        h, W1, nullptr, nullptr, b1, h2, M, H2, H1);

    // --- out = sigmoid(h2 @ W2^T + b2)  [M,16] fp32 ---
    head_kernel<<<M / 16, 256>>>(h2, W2, b2, out, M);
}

// round 9
// speedup vs baseline: 1.9151x; 1.0891x over previous
#include <cuda_runtime.h>
#include <cuda_fp16.h>
#include <math.h>
#include <stdint.h>

#define H1 128
#define H2 256
#define NCLS 16
#define MAXN 65536
#define MAXE 1048576

// ---- scratch (device globals: allocation-free per harness rules) ----
__device__ __align__(16) __half g_xh[MAXN * H1];      // x in fp16
__device__ __align__(16) __half g_y[MAXN * H1];       // relu(x@Wp^T+bp)
__device__ __align__(16) __half g_pooled[MAXN * H1];  // segment-max
__device__ __align__(16) __half g_h[MAXN * H1];       // combined hidden
__device__ __align__(16) __half g_h2[MAXN * H2];      // MLP hidden
__device__ __align__(16) __half g_wph[H1 * H1];       // fp16 weights
__device__ __align__(16) __half g_wsh[H1 * H1];
__device__ __align__(16) __half g_wnh[H1 * H1];
__device__ __align__(16) __half g_w1h[H2 * H1];
__device__ int g_hist[MAXN];
__device__ int g_offs[MAXN + 1];
__device__ int g_cursor[MAXN];
__device__ int g_ssrc[MAXE];

enum { ACT_RELU = 1, ACT_LEAKY = 2 };

__device__ __forceinline__ void mma_f16(
    float* c, const uint32_t* a, const uint32_t* b)
{
    asm volatile(
        "mma.sync.aligned.m16n8k16.row.col.f32.f16.f16.f32 "
        "{%0,%1,%2,%3}, {%4,%5,%6,%7}, {%8,%9}, {%0,%1,%2,%3};\n"
        : "+f"(c[0]), "+f"(c[1]), "+f"(c[2]), "+f"(c[3])
        : "r"(a[0]), "r"(a[1]), "r"(a[2]), "r"(a[3]),
          "r"(b[0]), "r"(b[1]));
}

__device__ __forceinline__ void ldsm_x4(
    uint32_t& r0, uint32_t& r1, uint32_t& r2, uint32_t& r3, uint32_t addr)
{
    asm volatile(
        "ldmatrix.sync.aligned.m8n8.x4.shared.b16 {%0,%1,%2,%3}, [%4];"
        : "=r"(r0), "=r"(r1), "=r"(r2), "=r"(r3) : "r"(addr));
}

#define CP_ASYNC16(dst, src) \
    asm volatile("cp.async.cg.shared.global [%0], [%1], 16;" \
                 :: "r"(dst), "l"(src))
#define CP_COMMIT() asm volatile("cp.async.commit_group;")

// fp32 -> fp16 elementwise (vectorized by 4)
__global__ void f2h_kernel(const float4* __restrict__ in,
                           uint2* __restrict__ out, int n4)
{
    int i = blockIdx.x * blockDim.x + threadIdx.x;
    if (i < n4) {
        float4 v = in[i];
        __half2 a = __floats2half2_rn(v.x, v.y);
        __half2 b = __floats2half2_rn(v.z, v.w);
        uint2 o;
        o.x = *(uint32_t*)&a;
        o.y = *(uint32_t*)&b;
        out[i] = o;
    }
}

// ============================================================================
// fp16 tensor-core GEMM, cp.async double-buffered, XOR-swizzled smem:
//   C[M,N](fp16) = act( A0[M,K] @ B0[N,K]^T (+ A1 @ B1^T) + bias[N] )
// All operands fp16. BM=BN=128, BK=64, 256 thr = 8 warps (2Mx4N), 64x32/warp.
// Dyn smem = 64 KB: A bufs @ {0,16K}, B bufs @ {32K,48K}; row = 128 B,
// 16B chunk c at byte ((c ^ (r&7))<<4).
// ============================================================================
template <int ACT, int NPASS>
__global__ void __launch_bounds__(256) gemm_h(
    const __half* __restrict__ A0, const __half* __restrict__ B0,
    const __half* __restrict__ A1, const __half* __restrict__ B1,
    const float* __restrict__ bias, __half* __restrict__ C,
    int M, int N, int K)
{
    extern __shared__ __align__(16) char dsm[];
    const uint32_t sbase = (uint32_t)__cvta_generic_to_shared(dsm);

    const int tid  = threadIdx.x;
    const int lane = tid & 31;
    const int warp = tid >> 5;
    const int wm = (warp & 1) * 64;
    const int wn = (warp >> 1) * 32;
    const int m0 = blockIdx.y * 128;
    const int n0 = blockIdx.x * 128;
    const int g  = lane >> 2;
    const int tg = lane & 3;

    const int KT = K / 64;
    const int T  = NPASS * KT;

    // staging indices (4 cp.async pairs per thread per tile)
    const int sr = tid >> 1;                 // rows tid/2 handled 2 chunks... 
    // per-thread: f = it*256+tid -> r=f>>3, c=f&7
    float acc[4][4][4];
    #pragma unroll
    for (int mi = 0; mi < 4; mi++)
        #pragma unroll
        for (int ni = 0; ni < 4; ni++)
            #pragma unroll
            for (int c = 0; c < 4; c++) acc[mi][ni][c] = 0.0f;
    (void)sr;

    auto load_tile = [&](int t, int buf) {
        int pass = (NPASS == 2) ? (t / KT) : 0;
        int k0 = (t - pass * KT) * 64;
        const __half* Ap = (NPASS == 2 && pass) ? A1 : A0;
        const __half* Bp = (NPASS == 2 && pass) ? B1 : B0;
        uint32_t abase = sbase + buf * 16384;
        uint32_t bbase = sbase + 32768 + buf * 16384;
        #pragma unroll
        for (int it = 0; it < 4; it++) {
            int f = it * 256 + tid;
            int r = f >> 3, c = f & 7;
            uint32_t soff = (uint32_t)(r * 128 + ((c ^ (r & 7)) << 4));
            CP_ASYNC16(abase + soff, Ap + (size_t)(m0 + r) * K + k0 + c * 8);
            CP_ASYNC16(bbase + soff, Bp + (size_t)(n0 + r) * K + k0 + c * 8);
        }
        CP_COMMIT();
    };

    load_tile(0, 0);
    int buf = 0;
    for (int t = 0; t < T; t++) {
        if (t + 1 < T) {
            load_tile(t + 1, buf ^ 1);
            asm volatile("cp.async.wait_group 1;");
        } else {
            asm volatile("cp.async.wait_group 0;");
        }
        __syncthreads();

        uint32_t abase = sbase + buf * 16384;
        uint32_t bbase = sbase + 32768 + buf * 16384;
        #pragma unroll
        for (int ks = 0; ks < 4; ks++) {
            const int kk = ks * 16;
            const int kcA = (kk >> 3) + (lane >> 4);
            const uint32_t aswz = (uint32_t)((kcA ^ (lane & 7)) << 4);
            uint32_t af[4][4];
            #pragma unroll
            for (int mi = 0; mi < 4; mi++)
                ldsm_x4(af[mi][0], af[mi][1], af[mi][2], af[mi][3],
                        abase + (uint32_t)((wm + mi * 16 + (lane & 15)) * 128)
                              + aswz);
            const int kcB = (kk >> 3) + ((lane >> 3) & 1);
            const uint32_t bswz = (uint32_t)((kcB ^ (lane & 7)) << 4);
            const int brow = wn + ((lane >> 4) & 1) * 8 + (lane & 7);
            uint32_t bf[4][2];
            #pragma unroll
            for (int nip = 0; nip < 2; nip++) {
                uint32_t r0, r1, r2, r3;
                ldsm_x4(r0, r1, r2, r3,
                        bbase + (uint32_t)((brow + nip * 16) * 128) + bswz);
                bf[2 * nip][0] = r0;     bf[2 * nip][1] = r1;
                bf[2 * nip + 1][0] = r2; bf[2 * nip + 1][1] = r3;
            }
            #pragma unroll
            for (int mi = 0; mi < 4; mi++)
                #pragma unroll
                for (int ni = 0; ni < 4; ni++)
                    mma_f16(acc[mi][ni], af[mi], bf[ni]);
        }
        __syncthreads();
        buf ^= 1;
    }

    // ---- epilogue ----
    #pragma unroll
    for (int mi = 0; mi < 4; mi++) {
        const int r0 = m0 + wm + mi * 16 + g;
        #pragma unroll
        for (int ni = 0; ni < 4; ni++) {
            const int col = n0 + wn + ni * 8 + tg * 2;
            const float b0 = bias[col], b1 = bias[col + 1];
            float v0 = acc[mi][ni][0] + b0;
            float v1 = acc[mi][ni][1] + b1;
            float v2 = acc[mi][ni][2] + b0;
            float v3 = acc[mi][ni][3] + b1;
            if (ACT == ACT_RELU) {
                v0 = fmaxf(v0, 0.f); v1 = fmaxf(v1, 0.f);
                v2 = fmaxf(v2, 0.f); v3 = fmaxf(v3, 0.f);
            }
            if (ACT == ACT_LEAKY) {
                v0 = (v0 > 0.f) ? v0 : 0.01f * v0;
                v1 = (v1 > 0.f) ? v1 : 0.01f * v1;
                v2 = (v2 > 0.f) ? v2 : 0.01f * v2;
                v3 = (v3 > 0.f) ? v3 : 0.01f * v3;
            }
            *reinterpret_cast<__half2*>(C + (size_t)r0 * N + col) =
                __floats2half2_rn(v0, v1);
            *reinterpret_cast<__half2*>(C + (size_t)(r0 + 8) * N + col) =
                __floats2half2_rn(v2, v3);
        }
    }
}

// ============================================================================
// Edge bucketing (counting sort by dst) + segmented max (fp16)
// ============================================================================
__global__ void hist_kernel(const int* __restrict__ dst, int* __restrict__ hist, int E)
{
    int i = blockIdx.x * blockDim.x + threadIdx.x;
    if (i < E) atomicAdd(&hist[dst[i]], 1);
}

__global__ void __launch_bounds__(1024) scan_kernel(
    const int* __restrict__ hist, int* __restrict__ offs,
    int* __restrict__ cursor, int N)
{
    __shared__ int part[1024];
    const int tid = threadIdx.x;
    const int per = N / 1024;
    const int base = tid * per;
    int s = 0;
    for (int i = 0; i < per; i++) s += hist[base + i];
    part[tid] = s;
    __syncthreads();
    for (int d = 1; d < 1024; d <<= 1) {
        int v = (tid >= d) ? part[tid - d] : 0;
        __syncthreads();
        part[tid] += v;
        __syncthreads();
    }
    int run = (tid == 0) ? 0 : part[tid - 1];
    for (int i = 0; i < per; i++) {
        offs[base + i] = run;
        cursor[base + i] = run;
        run += hist[base + i];
    }
    if (tid == 1023) offs[N] = run;
}

__global__ void scatter_edges(const int* __restrict__ src, const int* __restrict__ dst,
                              int* __restrict__ cursor, int* __restrict__ ssrc, int E)
{
    int i = blockIdx.x * blockDim.x + threadIdx.x;
    if (i < E) {
        int p = atomicAdd(&cursor[dst[i]], 1);
        ssrc[p] = src[i];
    }
}

// one warp per node; y rows = 128 halfs = 32 uint2 chunks, one per lane
__global__ void __launch_bounds__(256) pool_max(
    const uint2* __restrict__ y, const int* __restrict__ offs,
    const int* __restrict__ ssrc, uint2* __restrict__ pooled, int N)
{
    int w = (blockIdx.x * blockDim.x + threadIdx.x) >> 5;
    int lane = threadIdx.x & 31;
    if (w >= N) return;
    int e = offs[w], end = offs[w + 1];
    __half2 m0 = __float2half2_rn(0.f);
    __half2 m1 = m0;
    for (; e + 7 < end; e += 8) {
        uint2 v[8];
        #pragma unroll
        for (int j = 0; j < 8; j++)
            v[j] = y[(size_t)ssrc[e + j] * 32 + lane];
        #pragma unroll
        for (int j = 0; j < 8; j++) {
            m0 = __hmax2(m0, *(__half2*)&v[j].x);
            m1 = __hmax2(m1, *(__half2*)&v[j].y);
        }
    }
    for (; e < end; e++) {
        uint2 v0 = y[(size_t)ssrc[e] * 32 + lane];
        m0 = __hmax2(m0, *(__half2*)&v0.x);
        m1 = __hmax2(m1, *(__half2*)&v0.y);
    }
    uint2 o;
    o.x = *(uint32_t*)&m0;
    o.y = *(uint32_t*)&m1;
    pooled[(size_t)w * 32 + lane] = o;
}

// ============================================================================
// Head: out[M,16] = sigmoid(h2[M,256](fp16) @ W2[16,256]^T + b2)
// ============================================================================
__global__ void __launch_bounds__(256) head_kernel(
    const __half* __restrict__ h2, const float* __restrict__ W2,
    const float* __restrict__ b2, float* __restrict__ out, int M)
{
    __shared__ float ws[NCLS][H2 + 1];
    __shared__ float hs[16][H2 + 1];
    const int tid = threadIdx.x;
    const int m0 = blockIdx.x * 16;

    for (int i = tid; i < NCLS * H2; i += 256)
        ws[i / H2][i % H2] = W2[i];
    for (int i = tid; i < 16 * H2; i += 256)
        hs[i / H2][i % H2] = __half2float(h2[(size_t)m0 * H2 + i]);
    __syncthreads();

    const int r = tid >> 4;
    const int c = tid & 15;
    float acc = 0.0f;
    #pragma unroll 8
    for (int k = 0; k < H2; k++) acc += hs[r][k] * ws[c][k];
    acc += b2[c];
    out[(size_t)(m0 + r) * NCLS + c] = 1.0f / (1.0f + expf(-acc));
}

extern "C" void kernel_launch(void* const* d_in, const int* in_sizes, int n_in,
                              void* d_out, int out_size)
{
    const float* x  = (const float*)d_in[0];
    const float* Wp = (const float*)d_in[1];
    const float* bp = (const float*)d_in[2];
    const float* Ws = (const float*)d_in[3];
    const float* Wn = (const float*)d_in[4];
    const float* bn = (const float*)d_in[5];
    const float* W1 = (const float*)d_in[6];
    const float* b1 = (const float*)d_in[7];
    const float* W2 = (const float*)d_in[8];
    const float* b2 = (const float*)d_in[9];
    const int* src  = (const int*)d_in[10];
    const int* dst  = (const int*)d_in[11];
    float* out = (float*)d_out;

    const int M = in_sizes[0] / H1;   // IN_FEATS == H1 == 128
    const int E = in_sizes[10];

    __half *xh, *y, *pooled, *h, *h2, *wph, *wsh, *wnh, *w1h;
    int *hist, *offs, *cursor, *ssrc;
    cudaGetSymbolAddress((void**)&xh, g_xh);
    cudaGetSymbolAddress((void**)&y, g_y);
    cudaGetSymbolAddress((void**)&pooled, g_pooled);
    cudaGetSymbolAddress((void**)&h, g_h);
    cudaGetSymbolAddress((void**)&h2, g_h2);
    cudaGetSymbolAddress((void**)&wph, g_wph);
    cudaGetSymbolAddress((void**)&wsh, g_wsh);
    cudaGetSymbolAddress((void**)&wnh, g_wnh);
    cudaGetSymbolAddress((void**)&w1h, g_w1h);
    cudaGetSymbolAddress((void**)&hist, g_hist);
    cudaGetSymbolAddress((void**)&offs, g_offs);
    cudaGetSymbolAddress((void**)&cursor, g_cursor);
    cudaGetSymbolAddress((void**)&ssrc, g_ssrc);

    // opt-in to 64KB dynamic smem (idempotent)
    cudaFuncSetAttribute(gemm_h<ACT_RELU, 1>,
                         cudaFuncAttributeMaxDynamicSharedMemorySize, 65536);
    cudaFuncSetAttribute(gemm_h<ACT_LEAKY, 2>,
                         cudaFuncAttributeMaxDynamicSharedMemorySize, 65536);
    cudaFuncSetAttribute(gemm_h<ACT_LEAKY, 1>,
                         cudaFuncAttributeMaxDynamicSharedMemorySize, 65536);

    // one-time host-side resources for the graph fork (host objects only)
    static cudaStream_t s1 = nullptr;
    static cudaEvent_t evR = nullptr, evS = nullptr;
    if (s1 == nullptr) {
        cudaStreamCreateWithFlags(&s1, cudaStreamNonBlocking);
        cudaEventCreateWithFlags(&evR, cudaEventDisableTiming);
        cudaEventCreateWithFlags(&evS, cudaEventDisableTiming);
    }

    // ---- fork: edge bucketing on side stream ----
    cudaEventRecord(evR, 0);
    cudaStreamWaitEvent(s1, evR, 0);
    cudaMemsetAsync(hist, 0, M * sizeof(int), s1);
    hist_kernel<<<(E + 255) / 256, 256, 0, s1>>>(dst, hist, E);
    scan_kernel<<<1, 1024, 0, s1>>>(hist, offs, cursor, M);
    scatter_edges<<<(E + 255) / 256, 256, 0, s1>>>(src, dst, cursor, ssrc, E);
    cudaEventRecord(evS, s1);

    // ---- main stream: fp16 conversions ----
    int n4x = M * H1 / 4;
    f2h_kernel<<<(n4x + 255) / 256, 256>>>((const float4*)x, (uint2*)xh, n4x);
    f2h_kernel<<<(H1 * H1 / 4 + 255) / 256, 256>>>((const float4*)Wp, (uint2*)wph, H1 * H1 / 4);
    f2h_kernel<<<(H1 * H1 / 4 + 255) / 256, 256>>>((const float4*)Ws, (uint2*)wsh, H1 * H1 / 4);
    f2h_kernel<<<(H1 * H1 / 4 + 255) / 256, 256>>>((const float4*)Wn, (uint2*)wnh, H1 * H1 / 4);
    f2h_kernel<<<(H2 * H1 / 4 + 255) / 256, 256>>>((const float4*)W1, (uint2*)w1h, H2 * H1 / 4);

    // ---- y = relu(x @ Wp^T + bp)  [M,128] ----
    dim3 g1(1, M / 128);
    gemm_h<ACT_RELU, 1><<<g1, 256, 65536>>>(
        xh, wph, nullptr, nullptr, bp, y, M, H1, H1);

    // ---- join, then pooled[n] = segmented max ----
    cudaStreamWaitEvent(0, evS, 0);
    pool_max<<<(M + 7) / 8, 256>>>((const uint2*)y, offs, ssrc,
                                   (uint2*)pooled, M);

    // ---- h = leaky(x @ Ws^T + pooled @ Wn^T + bn)  [M,128] ----
    gemm_h<ACT_LEAKY, 2><<<g1, 256, 65536>>>(
        xh, wsh, pooled, wnh, bn, h, M, H1, H1);

    // ---- h2 = leaky(h @ W1^T + b1)  [M,256] ----
    dim3 g2(H2 / 128, M / 128);
    gemm_h<ACT_LEAKY, 1><<<g2, 256, 65536>>>(
        h, w1h, nullptr, nullptr, b1, h2, M, H2, H1);

    // ---- out = sigmoid(h2 @ W2^T + b2)  [M,16] ----
    head_kernel<<<M / 16, 256>>>(h2, W2, b2, out, M);
}

// round 11
// speedup vs baseline: 2.5290x; 1.3205x over previous
#include <cuda_runtime.h>
#include <cuda_fp16.h>
#include <math.h>
#include <stdint.h>

#define H1 128
#define H2 256
#define NCLS 16
#define MAXN 65536
#define MAXE 1048576

// ---- scratch (device globals: allocation-free per harness rules) ----
__device__ __align__(16) __half g_xh[MAXN * H1];      // x in fp16
__device__ __align__(16) __half g_y[MAXN * H1];       // relu(x@Wp^T+bp)
__device__ __align__(16) __half g_pooled[MAXN * H1];  // segment-max
__device__ __align__(16) __half g_h[MAXN * H1];       // combined hidden
__device__ __align__(16) __half g_wph[H1 * H1];       // fp16 weights
__device__ __align__(16) __half g_wsh[H1 * H1];
__device__ __align__(16) __half g_wnh[H1 * H1];
__device__ __align__(16) __half g_w1h[H2 * H1];
__device__ int g_hist[MAXN];
__device__ int g_offs[MAXN + 1];
__device__ int g_cursor[MAXN];
__device__ int g_ssrc[MAXE];

enum { ACT_RELU = 1, ACT_LEAKY = 2 };

__device__ __forceinline__ void mma_f16(
    float* c, const uint32_t* a, const uint32_t* b)
{
    asm volatile(
        "mma.sync.aligned.m16n8k16.row.col.f32.f16.f16.f32 "
        "{%0,%1,%2,%3}, {%4,%5,%6,%7}, {%8,%9}, {%0,%1,%2,%3};\n"
        : "+f"(c[0]), "+f"(c[1]), "+f"(c[2]), "+f"(c[3])
        : "r"(a[0]), "r"(a[1]), "r"(a[2]), "r"(a[3]),
          "r"(b[0]), "r"(b[1]));
}

__device__ __forceinline__ void ldsm_x4(
    uint32_t& r0, uint32_t& r1, uint32_t& r2, uint32_t& r3, uint32_t addr)
{
    asm volatile(
        "ldmatrix.sync.aligned.m8n8.x4.shared.b16 {%0,%1,%2,%3}, [%4];"
        : "=r"(r0), "=r"(r1), "=r"(r2), "=r"(r3) : "r"(addr));
}

#define CP_ASYNC16(dst, src) \
    asm volatile("cp.async.cg.shared.global [%0], [%1], 16;" \
                 :: "r"(dst), "l"(src))
#define CP_COMMIT() asm volatile("cp.async.commit_group;")

// one fused fp32 -> fp16 conversion: x, Wp, Ws, Wn, W1
__global__ void conv_all(
    const float4* __restrict__ x,  const float4* __restrict__ wp,
    const float4* __restrict__ ws, const float4* __restrict__ wn,
    const float4* __restrict__ w1,
    uint2* __restrict__ xh,  uint2* __restrict__ wph,
    uint2* __restrict__ wsh, uint2* __restrict__ wnh,
    uint2* __restrict__ w1h, int n4x)
{
    int i = blockIdx.x * blockDim.x + threadIdx.x;
    const float4* in;
    uint2* out;
    int j;
    if (i < n4x) { in = x; out = xh; j = i; }
    else {
        j = i - n4x;
        if      (j < 4096)  { in = wp; out = wph; }
        else if (j < 8192)  { in = ws; out = wsh; j -= 4096; }
        else if (j < 12288) { in = wn; out = wnh; j -= 8192; }
        else if (j < 20480) { in = w1; out = w1h; j -= 12288; }
        else return;
    }
    float4 v = in[j];
    __half2 a = __floats2half2_rn(v.x, v.y);
    __half2 b = __floats2half2_rn(v.z, v.w);
    uint2 o;
    o.x = *(uint32_t*)&a;
    o.y = *(uint32_t*)&b;
    out[j] = o;
}

// ============================================================================
// fp16 TC GEMM (unchanged from R7): C = act(A0@B0^T (+A1@B1^T) + bias), fp16 out
// BM=BN=128, BK=64, 256 thr. Dyn smem 64KB.
// ============================================================================
template <int ACT, int NPASS>
__global__ void __launch_bounds__(256) gemm_h(
    const __half* __restrict__ A0, const __half* __restrict__ B0,
    const __half* __restrict__ A1, const __half* __restrict__ B1,
    const float* __restrict__ bias, __half* __restrict__ C,
    int M, int N, int K)
{
    extern __shared__ __align__(16) char dsm[];
    const uint32_t sbase = (uint32_t)__cvta_generic_to_shared(dsm);

    const int tid  = threadIdx.x;
    const int lane = tid & 31;
    const int warp = tid >> 5;
    const int wm = (warp & 1) * 64;
    const int wn = (warp >> 1) * 32;
    const int m0 = blockIdx.y * 128;
    const int n0 = blockIdx.x * 128;
    const int g  = lane >> 2;
    const int tg = lane & 3;

    const int KT = K / 64;
    const int T  = NPASS * KT;

    float acc[4][4][4];
    #pragma unroll
    for (int mi = 0; mi < 4; mi++)
        #pragma unroll
        for (int ni = 0; ni < 4; ni++)
            #pragma unroll
            for (int c = 0; c < 4; c++) acc[mi][ni][c] = 0.0f;

    auto load_tile = [&](int t, int buf) {
        int pass = (NPASS == 2) ? (t / KT) : 0;
        int k0 = (t - pass * KT) * 64;
        const __half* Ap = (NPASS == 2 && pass) ? A1 : A0;
        const __half* Bp = (NPASS == 2 && pass) ? B1 : B0;
        uint32_t abase = sbase + buf * 16384;
        uint32_t bbase = sbase + 32768 + buf * 16384;
        #pragma unroll
        for (int it = 0; it < 4; it++) {
            int f = it * 256 + tid;
            int r = f >> 3, c = f & 7;
            uint32_t soff = (uint32_t)(r * 128 + ((c ^ (r & 7)) << 4));
            CP_ASYNC16(abase + soff, Ap + (size_t)(m0 + r) * K + k0 + c * 8);
            CP_ASYNC16(bbase + soff, Bp + (size_t)(n0 + r) * K + k0 + c * 8);
        }
        CP_COMMIT();
    };

    load_tile(0, 0);
    int buf = 0;
    for (int t = 0; t < T; t++) {
        if (t + 1 < T) {
            load_tile(t + 1, buf ^ 1);
            asm volatile("cp.async.wait_group 1;");
        } else {
            asm volatile("cp.async.wait_group 0;");
        }
        __syncthreads();

        uint32_t abase = sbase + buf * 16384;
        uint32_t bbase = sbase + 32768 + buf * 16384;
        #pragma unroll
        for (int ks = 0; ks < 4; ks++) {
            const int kk = ks * 16;
            const int kcA = (kk >> 3) + (lane >> 4);
            const uint32_t aswz = (uint32_t)((kcA ^ (lane & 7)) << 4);
            uint32_t af[4][4];
            #pragma unroll
            for (int mi = 0; mi < 4; mi++)
                ldsm_x4(af[mi][0], af[mi][1], af[mi][2], af[mi][3],
                        abase + (uint32_t)((wm + mi * 16 + (lane & 15)) * 128)
                              + aswz);
            const int kcB = (kk >> 3) + ((lane >> 3) & 1);
            const uint32_t bswz = (uint32_t)((kcB ^ (lane & 7)) << 4);
            const int brow = wn + ((lane >> 4) & 1) * 8 + (lane & 7);
            uint32_t bf[4][2];
            #pragma unroll
            for (int nip = 0; nip < 2; nip++) {
                uint32_t r0, r1, r2, r3;
                ldsm_x4(r0, r1, r2, r3,
                        bbase + (uint32_t)((brow + nip * 16) * 128) + bswz);
                bf[2 * nip][0] = r0;     bf[2 * nip][1] = r1;
                bf[2 * nip + 1][0] = r2; bf[2 * nip + 1][1] = r3;
            }
            #pragma unroll
            for (int mi = 0; mi < 4; mi++)
                #pragma unroll
                for (int ni = 0; ni < 4; ni++)
                    mma_f16(acc[mi][ni], af[mi], bf[ni]);
        }
        __syncthreads();
        buf ^= 1;
    }

    #pragma unroll
    for (int mi = 0; mi < 4; mi++) {
        const int r0 = m0 + wm + mi * 16 + g;
        #pragma unroll
        for (int ni = 0; ni < 4; ni++) {
            const int col = n0 + wn + ni * 8 + tg * 2;
            const float b0 = bias[col], b1 = bias[col + 1];
            float v0 = acc[mi][ni][0] + b0;
            float v1 = acc[mi][ni][1] + b1;
            float v2 = acc[mi][ni][2] + b0;
            float v3 = acc[mi][ni][3] + b1;
            if (ACT == ACT_RELU) {
                v0 = fmaxf(v0, 0.f); v1 = fmaxf(v1, 0.f);
                v2 = fmaxf(v2, 0.f); v3 = fmaxf(v3, 0.f);
            }
            if (ACT == ACT_LEAKY) {
                v0 = (v0 > 0.f) ? v0 : 0.01f * v0;
                v1 = (v1 > 0.f) ? v1 : 0.01f * v1;
                v2 = (v2 > 0.f) ? v2 : 0.01f * v2;
                v3 = (v3 > 0.f) ? v3 : 0.01f * v3;
            }
            *reinterpret_cast<__half2*>(C + (size_t)r0 * N + col) =
                __floats2half2_rn(v0, v1);
            *reinterpret_cast<__half2*>(C + (size_t)(r0 + 8) * N + col) =
                __floats2half2_rn(v2, v3);
        }
    }
}

// ============================================================================
// FUSED GEMM3 + head. 512 threads = 16 warps (2M x 8N), block = 128M x 256N.
//   h2_tile = leaky(h[128,128] @ W1[256,128]^T + b1)   -> smem only
//   out     = sigmoid(h2_tile @ W2[16,256]^T + b2)     -> gmem fp32
// Dyn smem 96KB: A bufs @{0,16K}; B bufs @{32K,64K}.
// Epilogue reuses smem: h2s (stride 264 halfs) @0, W2h @67584.
// ============================================================================
__global__ void __launch_bounds__(512) gemm3_head(
    const __half* __restrict__ A, const __half* __restrict__ B,
    const float* __restrict__ b1v, const float* __restrict__ W2,
    const float* __restrict__ b2v, float* __restrict__ out, int M)
{
    extern __shared__ __align__(16) char dsm[];
    const uint32_t sbase = (uint32_t)__cvta_generic_to_shared(dsm);
    const int K = 128;

    const int tid  = threadIdx.x;
    const int lane = tid & 31;
    const int warp = tid >> 5;
    const int wm = (warp & 1) * 64;
    const int wn = (warp >> 1) * 32;          // 0..224
    const int m0 = blockIdx.x * 128;
    const int g  = lane >> 2;
    const int tg = lane & 3;

    float acc[4][4][4];
    #pragma unroll
    for (int mi = 0; mi < 4; mi++)
        #pragma unroll
        for (int ni = 0; ni < 4; ni++)
            #pragma unroll
            for (int c = 0; c < 4; c++) acc[mi][ni][c] = 0.0f;

    auto load_tile = [&](int t, int buf) {
        int k0 = t * 64;
        uint32_t abase = sbase + buf * 16384;
        uint32_t bbase = sbase + 32768 + buf * 32768;
        #pragma unroll
        for (int it = 0; it < 2; it++) {              // A: 128 rows
            int f = it * 512 + tid;
            int r = f >> 3, c = f & 7;
            uint32_t soff = (uint32_t)(r * 128 + ((c ^ (r & 7)) << 4));
            CP_ASYNC16(abase + soff, A + (size_t)(m0 + r) * K + k0 + c * 8);
        }
        #pragma unroll
        for (int it = 0; it < 4; it++) {              // B: 256 rows
            int f = it * 512 + tid;
            int r = f >> 3, c = f & 7;
            uint32_t soff = (uint32_t)(r * 128 + ((c ^ (r & 7)) << 4));
            CP_ASYNC16(bbase + soff, B + (size_t)r * K + k0 + c * 8);
        }
        CP_COMMIT();
    };

    load_tile(0, 0);
    int buf = 0;
    for (int t = 0; t < 2; t++) {
        if (t == 0) {
            load_tile(1, 1);
            asm volatile("cp.async.wait_group 1;");
        } else {
            asm volatile("cp.async.wait_group 0;");
        }
        __syncthreads();

        uint32_t abase = sbase + buf * 16384;
        uint32_t bbase = sbase + 32768 + buf * 32768;
        #pragma unroll
        for (int ks = 0; ks < 4; ks++) {
            const int kk = ks * 16;
            const int kcA = (kk >> 3) + (lane >> 4);
            const uint32_t aswz = (uint32_t)((kcA ^ (lane & 7)) << 4);
            uint32_t af[4][4];
            #pragma unroll
            for (int mi = 0; mi < 4; mi++)
                ldsm_x4(af[mi][0], af[mi][1], af[mi][2], af[mi][3],
                        abase + (uint32_t)((wm + mi * 16 + (lane & 15)) * 128)
                              + aswz);
            const int kcB = (kk >> 3) + ((lane >> 3) & 1);
            const uint32_t bswz = (uint32_t)((kcB ^ (lane & 7)) << 4);
            const int brow = wn + ((lane >> 4) & 1) * 8 + (lane & 7);
            uint32_t bf[4][2];
            #pragma unroll
            for (int nip = 0; nip < 2; nip++) {
                uint32_t r0, r1, r2, r3;
                ldsm_x4(r0, r1, r2, r3,
                        bbase + (uint32_t)((brow + nip * 16) * 128) + bswz);
                bf[2 * nip][0] = r0;     bf[2 * nip][1] = r1;
                bf[2 * nip + 1][0] = r2; bf[2 * nip + 1][1] = r3;
            }
            #pragma unroll
            for (int mi = 0; mi < 4; mi++)
                #pragma unroll
                for (int ni = 0; ni < 4; ni++)
                    mma_f16(acc[mi][ni], af[mi], bf[ni]);
        }
        __syncthreads();
        buf ^= 1;
    }

    // ---- epilogue phase 1: leaky(h2)+b1 into smem (stride 264 halfs) ----
    __half* h2s = reinterpret_cast<__half*>(dsm);
    __half* w2s = h2s + 128 * 264;            // 16 x 264
    #pragma unroll
    for (int mi = 0; mi < 4; mi++) {
        const int r0 = wm + mi * 16 + g;
        #pragma unroll
        for (int ni = 0; ni < 4; ni++) {
            const int col = wn + ni * 8 + tg * 2;
            const float b0 = b1v[col], b1 = b1v[col + 1];
            float v0 = acc[mi][ni][0] + b0;
            float v1 = acc[mi][ni][1] + b1;
            float v2 = acc[mi][ni][2] + b0;
            float v3 = acc[mi][ni][3] + b1;
            v0 = (v0 > 0.f) ? v0 : 0.01f * v0;
            v1 = (v1 > 0.f) ? v1 : 0.01f * v1;
            v2 = (v2 > 0.f) ? v2 : 0.01f * v2;
            v3 = (v3 > 0.f) ? v3 : 0.01f * v3;
            *reinterpret_cast<__half2*>(&h2s[r0 * 264 + col]) =
                __floats2half2_rn(v0, v1);
            *reinterpret_cast<__half2*>(&h2s[(r0 + 8) * 264 + col]) =
                __floats2half2_rn(v2, v3);
        }
    }
    // W2 (16x256 fp32) -> fp16 smem
    #pragma unroll
    for (int it = 0; it < 2; it++) {
        int f = it * 512 + tid;               // 0..1023 float4 chunks
        int crow = f >> 6;
        int k = (f & 63) * 4;
        float4 v = reinterpret_cast<const float4*>(W2)[f];
        *reinterpret_cast<__half2*>(&w2s[crow * 264 + k]) =
            __floats2half2_rn(v.x, v.y);
        *reinterpret_cast<__half2*>(&w2s[crow * 264 + k + 2]) =
            __floats2half2_rn(v.z, v.w);
    }
    __syncthreads();

    // ---- epilogue phase 2: head MMA (warps 0..7, 16 rows each) ----
    if (warp < 8) {
        float ao[2][4];
        #pragma unroll
        for (int ni = 0; ni < 2; ni++)
            #pragma unroll
            for (int c = 0; c < 4; c++) ao[ni][c] = 0.0f;

        const uint32_t hb = sbase;
        const uint32_t wb = sbase + 67584 * 2 / 2 * 2;  // 67584 halfs? no:
        // w2s is at half-index 128*264 = 33792 -> byte offset 67584
        const uint32_t wbb = sbase + 67584;
        const int arow = warp * 16 + (lane & 15);
        const int ahalf = (lane >> 4) * 8;
        const int brow = ((lane >> 4) & 1) * 8 + (lane & 7);
        const int bhalf = ((lane >> 3) & 1) * 8;
        (void)wb;
        #pragma unroll
        for (int ks = 0; ks < 16; ks++) {
            const int kk = ks * 16;
            uint32_t af[4];
            ldsm_x4(af[0], af[1], af[2], af[3],
                    hb + (uint32_t)(arow * 264 + kk + ahalf) * 2);
            uint32_t r0, r1, r2, r3;
            ldsm_x4(r0, r1, r2, r3,
                    wbb + (uint32_t)(brow * 264 + kk + bhalf) * 2);
            uint32_t bf0[2] = {r0, r1}, bf1[2] = {r2, r3};
            mma_f16(ao[0], af, bf0);
            mma_f16(ao[1], af, bf1);
        }
        const int m = m0 + warp * 16 + g;
        #pragma unroll
        for (int ni = 0; ni < 2; ni++) {
            const int col = ni * 8 + tg * 2;
            const float c0 = b2v[col], c1 = b2v[col + 1];
            float s0 = 1.0f / (1.0f + expf(-(ao[ni][0] + c0)));
            float s1 = 1.0f / (1.0f + expf(-(ao[ni][1] + c1)));
            float s2 = 1.0f / (1.0f + expf(-(ao[ni][2] + c0)));
            float s3 = 1.0f / (1.0f + expf(-(ao[ni][3] + c1)));
            *reinterpret_cast<float2*>(out + (size_t)m * NCLS + col) =
                make_float2(s0, s1);
            *reinterpret_cast<float2*>(out + (size_t)(m + 8) * NCLS + col) =
                make_float2(s2, s3);
        }
    }
}

// ============================================================================
// Edge bucketing + segmented max (unchanged)
// ============================================================================
__global__ void hist_kernel(const int* __restrict__ dst, int* __restrict__ hist, int E)
{
    int i = blockIdx.x * blockDim.x + threadIdx.x;
    if (i < E) atomicAdd(&hist[dst[i]], 1);
}

__global__ void __launch_bounds__(1024) scan_kernel(
    const int* __restrict__ hist, int* __restrict__ offs,
    int* __restrict__ cursor, int N)
{
    __shared__ int part[1024];
    const int tid = threadIdx.x;
    const int per = N / 1024;
    const int base = tid * per;
    int s = 0;
    for (int i = 0; i < per; i++) s += hist[base + i];
    part[tid] = s;
    __syncthreads();
    for (int d = 1; d < 1024; d <<= 1) {
        int v = (tid >= d) ? part[tid - d] : 0;
        __syncthreads();
        part[tid] += v;
        __syncthreads();
    }
    int run = (tid == 0) ? 0 : part[tid - 1];
    for (int i = 0; i < per; i++) {
        offs[base + i] = run;
        cursor[base + i] = run;
        run += hist[base + i];
    }
    if (tid == 1023) offs[N] = run;
}

__global__ void scatter_edges(const int* __restrict__ src, const int* __restrict__ dst,
                              int* __restrict__ cursor, int* __restrict__ ssrc, int E)
{
    int i = blockIdx.x * blockDim.x + threadIdx.x;
    if (i < E) {
        int p = atomicAdd(&cursor[dst[i]], 1);
        ssrc[p] = src[i];
    }
}

__global__ void __launch_bounds__(256) pool_max(
    const uint2* __restrict__ y, const int* __restrict__ offs,
    const int* __restrict__ ssrc, uint2* __restrict__ pooled, int N)
{
    int w = (blockIdx.x * blockDim.x + threadIdx.x) >> 5;
    int lane = threadIdx.x & 31;
    if (w >= N) return;
    int e = offs[w], end = offs[w + 1];
    __half2 m0 = __float2half2_rn(0.f);
    __half2 m1 = m0;
    for (; e + 7 < end; e += 8) {
        uint2 v[8];
        #pragma unroll
        for (int j = 0; j < 8; j++)
            v[j] = y[(size_t)ssrc[e + j] * 32 + lane];
        #pragma unroll
        for (int j = 0; j < 8; j++) {
            m0 = __hmax2(m0, *(__half2*)&v[j].x);
            m1 = __hmax2(m1, *(__half2*)&v[j].y);
        }
    }
    for (; e < end; e++) {
        uint2 v0 = y[(size_t)ssrc[e] * 32 + lane];
        m0 = __hmax2(m0, *(__half2*)&v0.x);
        m1 = __hmax2(m1, *(__half2*)&v0.y);
    }
    uint2 o;
    o.x = *(uint32_t*)&m0;
    o.y = *(uint32_t*)&m1;
    pooled[(size_t)w * 32 + lane] = o;
}

extern "C" void kernel_launch(void* const* d_in, const int* in_sizes, int n_in,
                              void* d_out, int out_size)
{
    const float* x  = (const float*)d_in[0];
    const float* Wp = (const float*)d_in[1];
    const float* bp = (const float*)d_in[2];
    const float* Ws = (const float*)d_in[3];
    const float* Wn = (const float*)d_in[4];
    const float* bn = (const float*)d_in[5];
    const float* W1 = (const float*)d_in[6];
    const float* b1 = (const float*)d_in[7];
    const float* W2 = (const float*)d_in[8];
    const float* b2 = (const float*)d_in[9];
    const int* src  = (const int*)d_in[10];
    const int* dst  = (const int*)d_in[11];
    float* out = (float*)d_out;

    const int M = in_sizes[0] / H1;   // IN_FEATS == H1 == 128
    const int E = in_sizes[10];

    __half *xh, *y, *pooled, *h, *wph, *wsh, *wnh, *w1h;
    int *hist, *offs, *cursor, *ssrc;
    cudaGetSymbolAddress((void**)&xh, g_xh);
    cudaGetSymbolAddress((void**)&y, g_y);
    cudaGetSymbolAddress((void**)&pooled, g_pooled);
    cudaGetSymbolAddress((void**)&h, g_h);
    cudaGetSymbolAddress((void**)&wph, g_wph);
    cudaGetSymbolAddress((void**)&wsh, g_wsh);
    cudaGetSymbolAddress((void**)&wnh, g_wnh);
    cudaGetSymbolAddress((void**)&w1h, g_w1h);
    cudaGetSymbolAddress((void**)&hist, g_hist);
    cudaGetSymbolAddress((void**)&offs, g_offs);
    cudaGetSymbolAddress((void**)&cursor, g_cursor);
    cudaGetSymbolAddress((void**)&ssrc, g_ssrc);

    cudaFuncSetAttribute(gemm_h<ACT_RELU, 1>,
                         cudaFuncAttributeMaxDynamicSharedMemorySize, 65536);
    cudaFuncSetAttribute(gemm_h<ACT_LEAKY, 2>,
                         cudaFuncAttributeMaxDynamicSharedMemorySize, 65536);
    cudaFuncSetAttribute(gemm3_head,
                         cudaFuncAttributeMaxDynamicSharedMemorySize, 98304);

    static cudaStream_t s1 = nullptr;
    static cudaEvent_t evR = nullptr, evS = nullptr;
    if (s1 == nullptr) {
        cudaStreamCreateWithFlags(&s1, cudaStreamNonBlocking);
        cudaEventCreateWithFlags(&evR, cudaEventDisableTiming);
        cudaEventCreateWithFlags(&evS, cudaEventDisableTiming);
    }

    // ---- fork: edge bucketing on side stream ----
    cudaEventRecord(evR, 0);
    cudaStreamWaitEvent(s1, evR, 0);
    cudaMemsetAsync(hist, 0, M * sizeof(int), s1);
    hist_kernel<<<(E + 255) / 256, 256, 0, s1>>>(dst, hist, E);
    scan_kernel<<<1, 1024, 0, s1>>>(hist, offs, cursor, M);
    scatter_edges<<<(E + 255) / 256, 256, 0, s1>>>(src, dst, cursor, ssrc, E);
    cudaEventRecord(evS, s1);

    // ---- main: one fused fp16 conversion ----
    int n4x = M * H1 / 4;
    int n4tot = n4x + 20480;
    conv_all<<<(n4tot + 255) / 256, 256>>>(
        (const float4*)x, (const float4*)Wp, (const float4*)Ws,
        (const float4*)Wn, (const float4*)W1,
        (uint2*)xh, (uint2*)wph, (uint2*)wsh, (uint2*)wnh, (uint2*)w1h, n4x);

    // ---- y = relu(x @ Wp^T + bp) ----
    dim3 g1(1, M / 128);
    gemm_h<ACT_RELU, 1><<<g1, 256, 65536>>>(
        xh, wph, nullptr, nullptr, bp, y, M, H1, H1);

    // ---- join, pooled = segmented max ----
    cudaStreamWaitEvent(0, evS, 0);
    pool_max<<<(M + 7) / 8, 256>>>((const uint2*)y, offs, ssrc,
                                   (uint2*)pooled, M);

    // ---- h = leaky(x @ Ws^T + pooled @ Wn^T + bn) ----
    gemm_h<ACT_LEAKY, 2><<<g1, 256, 65536>>>(
        xh, wsh, pooled, wnh, bn, h, M, H1, H1);

    // ---- fused: h2 = leaky(h @ W1^T + b1); out = sigmoid(h2 @ W2^T + b2) ----
    gemm3_head<<<M / 128, 512, 98304>>>(h, w1h, b1, W2, b2, out, M);
}

// round 12
// speedup vs baseline: 2.6007x; 1.0284x over previous
#include <cuda_runtime.h>
#include <cuda_fp16.h>
#include <math.h>
#include <stdint.h>

#define H1 128
#define H2 256
#define NCLS 16
#define MAXN 65536
#define MAXE 1048576

// ---- scratch (device globals: allocation-free per harness rules) ----
__device__ __align__(16) __half g_xh[MAXN * H1];      // x in fp16
__device__ __align__(16) __half g_y[MAXN * H1];       // relu(x@Wp^T+bp)
__device__ __align__(16) __half g_pooled[MAXN * H1];  // segment-max
__device__ __align__(16) __half g_wph[H1 * H1];       // fp16 weights
__device__ __align__(16) __half g_wsh[H1 * H1];
__device__ __align__(16) __half g_wnh[H1 * H1];
__device__ __align__(16) __half g_w1h[H2 * H1];
__device__ int g_hist[MAXN];
__device__ int g_offs[MAXN + 1];
__device__ int g_cursor[MAXN];
__device__ int g_ssrc[MAXE];

enum { ACT_RELU = 1, ACT_LEAKY = 2 };

__device__ __forceinline__ void mma_f16(
    float* c, const uint32_t* a, const uint32_t* b)
{
    asm volatile(
        "mma.sync.aligned.m16n8k16.row.col.f32.f16.f16.f32 "
        "{%0,%1,%2,%3}, {%4,%5,%6,%7}, {%8,%9}, {%0,%1,%2,%3};\n"
        : "+f"(c[0]), "+f"(c[1]), "+f"(c[2]), "+f"(c[3])
        : "r"(a[0]), "r"(a[1]), "r"(a[2]), "r"(a[3]),
          "r"(b[0]), "r"(b[1]));
}

__device__ __forceinline__ void ldsm_x4(
    uint32_t& r0, uint32_t& r1, uint32_t& r2, uint32_t& r3, uint32_t addr)
{
    asm volatile(
        "ldmatrix.sync.aligned.m8n8.x4.shared.b16 {%0,%1,%2,%3}, [%4];"
        : "=r"(r0), "=r"(r1), "=r"(r2), "=r"(r3) : "r"(addr));
}

#define CP_ASYNC16(dst, src) \
    asm volatile("cp.async.cg.shared.global [%0], [%1], 16;" \
                 :: "r"(dst), "l"(src))
#define CP_COMMIT() asm volatile("cp.async.commit_group;")

// one fused fp32 -> fp16 conversion: x, Wp, Ws, Wn, W1
__global__ void conv_all(
    const float4* __restrict__ x,  const float4* __restrict__ wp,
    const float4* __restrict__ ws, const float4* __restrict__ wn,
    const float4* __restrict__ w1,
    uint2* __restrict__ xh,  uint2* __restrict__ wph,
    uint2* __restrict__ wsh, uint2* __restrict__ wnh,
    uint2* __restrict__ w1h, int n4x)
{
    int i = blockIdx.x * blockDim.x + threadIdx.x;
    const float4* in;
    uint2* out;
    int j;
    if (i < n4x) { in = x; out = xh; j = i; }
    else {
        j = i - n4x;
        if      (j < 4096)  { in = wp; out = wph; }
        else if (j < 8192)  { in = ws; out = wsh; j -= 4096; }
        else if (j < 12288) { in = wn; out = wnh; j -= 8192; }
        else if (j < 20480) { in = w1; out = w1h; j -= 12288; }
        else return;
    }
    float4 v = in[j];
    __half2 a = __floats2half2_rn(v.x, v.y);
    __half2 b = __floats2half2_rn(v.z, v.w);
    uint2 o;
    o.x = *(uint32_t*)&a;
    o.y = *(uint32_t*)&b;
    out[j] = o;
}

// ============================================================================
// GEMM1: y = relu(x @ Wp^T + bp), fp16 in/out (unchanged, 256 thr, 64KB smem)
// ============================================================================
template <int ACT, int NPASS>
__global__ void __launch_bounds__(256) gemm_h(
    const __half* __restrict__ A0, const __half* __restrict__ B0,
    const __half* __restrict__ A1, const __half* __restrict__ B1,
    const float* __restrict__ bias, __half* __restrict__ C,
    int M, int N, int K)
{
    extern __shared__ __align__(16) char dsm[];
    const uint32_t sbase = (uint32_t)__cvta_generic_to_shared(dsm);

    const int tid  = threadIdx.x;
    const int lane = tid & 31;
    const int warp = tid >> 5;
    const int wm = (warp & 1) * 64;
    const int wn = (warp >> 1) * 32;
    const int m0 = blockIdx.y * 128;
    const int n0 = blockIdx.x * 128;
    const int g  = lane >> 2;
    const int tg = lane & 3;

    const int KT = K / 64;
    const int T  = NPASS * KT;

    float acc[4][4][4];
    #pragma unroll
    for (int mi = 0; mi < 4; mi++)
        #pragma unroll
        for (int ni = 0; ni < 4; ni++)
            #pragma unroll
            for (int c = 0; c < 4; c++) acc[mi][ni][c] = 0.0f;

    auto load_tile = [&](int t, int buf) {
        int pass = (NPASS == 2) ? (t / KT) : 0;
        int k0 = (t - pass * KT) * 64;
        const __half* Ap = (NPASS == 2 && pass) ? A1 : A0;
        const __half* Bp = (NPASS == 2 && pass) ? B1 : B0;
        uint32_t abase = sbase + buf * 16384;
        uint32_t bbase = sbase + 32768 + buf * 16384;
        #pragma unroll
        for (int it = 0; it < 4; it++) {
            int f = it * 256 + tid;
            int r = f >> 3, c = f & 7;
            uint32_t soff = (uint32_t)(r * 128 + ((c ^ (r & 7)) << 4));
            CP_ASYNC16(abase + soff, Ap + (size_t)(m0 + r) * K + k0 + c * 8);
            CP_ASYNC16(bbase + soff, Bp + (size_t)(n0 + r) * K + k0 + c * 8);
        }
        CP_COMMIT();
    };

    load_tile(0, 0);
    int buf = 0;
    for (int t = 0; t < T; t++) {
        if (t + 1 < T) {
            load_tile(t + 1, buf ^ 1);
            asm volatile("cp.async.wait_group 1;");
        } else {
            asm volatile("cp.async.wait_group 0;");
        }
        __syncthreads();

        uint32_t abase = sbase + buf * 16384;
        uint32_t bbase = sbase + 32768 + buf * 16384;
        #pragma unroll
        for (int ks = 0; ks < 4; ks++) {
            const int kk = ks * 16;
            const int kcA = (kk >> 3) + (lane >> 4);
            const uint32_t aswz = (uint32_t)((kcA ^ (lane & 7)) << 4);
            uint32_t af[4][4];
            #pragma unroll
            for (int mi = 0; mi < 4; mi++)
                ldsm_x4(af[mi][0], af[mi][1], af[mi][2], af[mi][3],
                        abase + (uint32_t)((wm + mi * 16 + (lane & 15)) * 128)
                              + aswz);
            const int kcB = (kk >> 3) + ((lane >> 3) & 1);
            const uint32_t bswz = (uint32_t)((kcB ^ (lane & 7)) << 4);
            const int brow = wn + ((lane >> 4) & 1) * 8 + (lane & 7);
            uint32_t bf[4][2];
            #pragma unroll
            for (int nip = 0; nip < 2; nip++) {
                uint32_t r0, r1, r2, r3;
                ldsm_x4(r0, r1, r2, r3,
                        bbase + (uint32_t)((brow + nip * 16) * 128) + bswz);
                bf[2 * nip][0] = r0;     bf[2 * nip][1] = r1;
                bf[2 * nip + 1][0] = r2; bf[2 * nip + 1][1] = r3;
            }
            #pragma unroll
            for (int mi = 0; mi < 4; mi++)
                #pragma unroll
                for (int ni = 0; ni < 4; ni++)
                    mma_f16(acc[mi][ni], af[mi], bf[ni]);
        }
        __syncthreads();
        buf ^= 1;
    }

    #pragma unroll
    for (int mi = 0; mi < 4; mi++) {
        const int r0 = m0 + wm + mi * 16 + g;
        #pragma unroll
        for (int ni = 0; ni < 4; ni++) {
            const int col = n0 + wn + ni * 8 + tg * 2;
            const float b0 = bias[col], b1 = bias[col + 1];
            float v0 = acc[mi][ni][0] + b0;
            float v1 = acc[mi][ni][1] + b1;
            float v2 = acc[mi][ni][2] + b0;
            float v3 = acc[mi][ni][3] + b1;
            if (ACT == ACT_RELU) {
                v0 = fmaxf(v0, 0.f); v1 = fmaxf(v1, 0.f);
                v2 = fmaxf(v2, 0.f); v3 = fmaxf(v3, 0.f);
            }
            if (ACT == ACT_LEAKY) {
                v0 = (v0 > 0.f) ? v0 : 0.01f * v0;
                v1 = (v1 > 0.f) ? v1 : 0.01f * v1;
                v2 = (v2 > 0.f) ? v2 : 0.01f * v2;
                v3 = (v3 > 0.f) ? v3 : 0.01f * v3;
            }
            *reinterpret_cast<__half2*>(C + (size_t)r0 * N + col) =
                __floats2half2_rn(v0, v1);
            *reinterpret_cast<__half2*>(C + (size_t)(r0 + 8) * N + col) =
                __floats2half2_rn(v2, v3);
        }
    }
}

// ============================================================================
// FUSED TAIL: per 128-row block, entirely on-chip after pooled:
//   Phase A: h   = leaky(x@Ws^T + pooled@Wn^T + bn)    -> smem h_s
//   Phase B: h2  = leaky(h_s@W1^T + b1)                -> smem h2s
//   Phase C: out = sigmoid(h2s@W2^T + b2)              -> gmem fp32
// 512 threads = 16 warps. Dyn smem 100 KB:
//   h_s  @ 0       : 128 x 136 halfs (34816 B)
//   A/B double bufs & W1 bufs @ 36864..102400
//   h2s  @ 0       : 128 x 264 halfs (67584 B)   [after phase B MMAs]
//   w2s  @ 67584   : 16 x 264 halfs (8448 B)
// ============================================================================
__global__ void __launch_bounds__(512) fused_tail(
    const __half* __restrict__ X,  const __half* __restrict__ Wsh,
    const __half* __restrict__ P,  const __half* __restrict__ Wnh,
    const float* __restrict__ bn,  const __half* __restrict__ W1h,
    const float* __restrict__ b1v, const float* __restrict__ W2,
    const float* __restrict__ b2v, float* __restrict__ out, int M)
{
    extern __shared__ __align__(16) char dsm[];
    const uint32_t sbase = (uint32_t)__cvta_generic_to_shared(dsm);
    const int K = 128, LH = 136;          // h_s stride in halfs

    const int tid  = threadIdx.x;
    const int lane = tid & 31;
    const int warp = tid >> 5;
    const int m0 = blockIdx.x * 128;
    const int g  = lane >> 2;
    const int tg = lane & 3;

    __half* h_s = reinterpret_cast<__half*>(dsm);

    // ---------------- Phase A: h = leaky(x@Ws^T + pooled@Wn^T + bn) ---------
    {
        const int wmA = (warp & 3) * 32;
        const int wnA = (warp >> 2) * 32;

        float acc[2][4][4];
        #pragma unroll
        for (int mi = 0; mi < 2; mi++)
            #pragma unroll
            for (int ni = 0; ni < 4; ni++)
                #pragma unroll
                for (int c = 0; c < 4; c++) acc[mi][ni][c] = 0.0f;

        auto load_tile = [&](int t, int buf) {
            int pass = t >> 1;
            int k0 = (t & 1) * 64;
            const __half* Ap = pass ? P : X;
            const __half* Bp = pass ? Wnh : Wsh;
            uint32_t abase = sbase + 36864 + buf * 16384;
            uint32_t bbase = sbase + 36864 + 32768 + buf * 16384;
            #pragma unroll
            for (int it = 0; it < 2; it++) {
                int f = it * 512 + tid;
                int r = f >> 3, c = f & 7;
                uint32_t soff = (uint32_t)(r * 128 + ((c ^ (r & 7)) << 4));
                CP_ASYNC16(abase + soff, Ap + (size_t)(m0 + r) * K + k0 + c * 8);
                CP_ASYNC16(bbase + soff, Bp + (size_t)r * K + k0 + c * 8);
            }
            CP_COMMIT();
        };

        load_tile(0, 0);
        int buf = 0;
        for (int t = 0; t < 4; t++) {
            if (t + 1 < 4) {
                load_tile(t + 1, buf ^ 1);
                asm volatile("cp.async.wait_group 1;");
            } else {
                asm volatile("cp.async.wait_group 0;");
            }
            __syncthreads();

            uint32_t abase = sbase + 36864 + buf * 16384;
            uint32_t bbase = sbase + 36864 + 32768 + buf * 16384;
            #pragma unroll
            for (int ks = 0; ks < 4; ks++) {
                const int kk = ks * 16;
                const int kcA = (kk >> 3) + (lane >> 4);
                const uint32_t aswz = (uint32_t)((kcA ^ (lane & 7)) << 4);
                uint32_t af[2][4];
                #pragma unroll
                for (int mi = 0; mi < 2; mi++)
                    ldsm_x4(af[mi][0], af[mi][1], af[mi][2], af[mi][3],
                            abase + (uint32_t)((wmA + mi * 16 + (lane & 15)) * 128)
                                  + aswz);
                const int kcB = (kk >> 3) + ((lane >> 3) & 1);
                const uint32_t bswz = (uint32_t)((kcB ^ (lane & 7)) << 4);
                const int brow = wnA + ((lane >> 4) & 1) * 8 + (lane & 7);
                uint32_t bf[4][2];
                #pragma unroll
                for (int nip = 0; nip < 2; nip++) {
                    uint32_t r0, r1, r2, r3;
                    ldsm_x4(r0, r1, r2, r3,
                            bbase + (uint32_t)((brow + nip * 16) * 128) + bswz);
                    bf[2 * nip][0] = r0;     bf[2 * nip][1] = r1;
                    bf[2 * nip + 1][0] = r2; bf[2 * nip + 1][1] = r3;
                }
                #pragma unroll
                for (int mi = 0; mi < 2; mi++)
                    #pragma unroll
                    for (int ni = 0; ni < 4; ni++)
                        mma_f16(acc[mi][ni], af[mi], bf[ni]);
            }
            __syncthreads();
            buf ^= 1;
        }

        // prefetch W1 (256x128 fp16) into smem @36864 as two 64-col chunks,
        // overlapping with the h_s epilogue below
        #pragma unroll
        for (int kt = 0; kt < 2; kt++) {
            uint32_t wbase = sbase + 36864 + kt * 32768;
            #pragma unroll
            for (int it = 0; it < 4; it++) {
                int f = it * 512 + tid;
                int r = f >> 3, c = f & 7;   // r 0..255
                uint32_t soff = (uint32_t)(r * 128 + ((c ^ (r & 7)) << 4));
                CP_ASYNC16(wbase + soff, W1h + (size_t)r * K + kt * 64 + c * 8);
            }
        }
        CP_COMMIT();

        // h epilogue -> h_s (stride 136 halfs)
        #pragma unroll
        for (int mi = 0; mi < 2; mi++) {
            const int r0 = wmA + mi * 16 + g;
            #pragma unroll
            for (int ni = 0; ni < 4; ni++) {
                const int col = wnA + ni * 8 + tg * 2;
                const float c0 = bn[col], c1 = bn[col + 1];
                float v0 = acc[mi][ni][0] + c0;
                float v1 = acc[mi][ni][1] + c1;
                float v2 = acc[mi][ni][2] + c0;
                float v3 = acc[mi][ni][3] + c1;
                v0 = (v0 > 0.f) ? v0 : 0.01f * v0;
                v1 = (v1 > 0.f) ? v1 : 0.01f * v1;
                v2 = (v2 > 0.f) ? v2 : 0.01f * v2;
                v3 = (v3 > 0.f) ? v3 : 0.01f * v3;
                *reinterpret_cast<__half2*>(&h_s[r0 * LH + col]) =
                    __floats2half2_rn(v0, v1);
                *reinterpret_cast<__half2*>(&h_s[(r0 + 8) * LH + col]) =
                    __floats2half2_rn(v2, v3);
            }
        }
        asm volatile("cp.async.wait_group 0;");
        __syncthreads();
    }

    // ---------------- Phase B: h2 = leaky(h_s @ W1^T + b1) ------------------
    const int wmB = (warp & 1) * 64;
    const int wnB = (warp >> 1) * 32;

    float accB[4][4][4];
    #pragma unroll
    for (int mi = 0; mi < 4; mi++)
        #pragma unroll
        for (int ni = 0; ni < 4; ni++)
            #pragma unroll
            for (int c = 0; c < 4; c++) accB[mi][ni][c] = 0.0f;

    #pragma unroll
    for (int kt = 0; kt < 2; kt++) {
        uint32_t bbase = sbase + 36864 + kt * 32768;
        #pragma unroll
        for (int ks = 0; ks < 4; ks++) {
            const int kk = ks * 16;
            uint32_t af[4][4];
            #pragma unroll
            for (int mi = 0; mi < 4; mi++) {
                int arow = wmB + mi * 16 + (lane & 15);
                uint32_t addr = sbase +
                    (uint32_t)(arow * LH + kt * 64 + kk + (lane >> 4) * 8) * 2;
                ldsm_x4(af[mi][0], af[mi][1], af[mi][2], af[mi][3], addr);
            }
            const int kcB = (kk >> 3) + ((lane >> 3) & 1);
            const uint32_t bswz = (uint32_t)((kcB ^ (lane & 7)) << 4);
            const int brow = wnB + ((lane >> 4) & 1) * 8 + (lane & 7);
            uint32_t bf[4][2];
            #pragma unroll
            for (int nip = 0; nip < 2; nip++) {
                uint32_t r0, r1, r2, r3;
                ldsm_x4(r0, r1, r2, r3,
                        bbase + (uint32_t)((brow + nip * 16) * 128) + bswz);
                bf[2 * nip][0] = r0;     bf[2 * nip][1] = r1;
                bf[2 * nip + 1][0] = r2; bf[2 * nip + 1][1] = r3;
            }
            #pragma unroll
            for (int mi = 0; mi < 4; mi++)
                #pragma unroll
                for (int ni = 0; ni < 4; ni++)
                    mma_f16(accB[mi][ni], af[mi], bf[ni]);
        }
    }
    __syncthreads();   // h_s & W1 bufs dead; h2s/w2s may overwrite

    // h2 epilogue -> h2s (stride 264), and stage W2 -> w2s fp16
    __half* h2s = reinterpret_cast<__half*>(dsm);
    __half* w2s = h2s + 128 * 264;
    #pragma unroll
    for (int mi = 0; mi < 4; mi++) {
        const int r0 = wmB + mi * 16 + g;
        #pragma unroll
        for (int ni = 0; ni < 4; ni++) {
            const int col = wnB + ni * 8 + tg * 2;
            const float c0 = b1v[col], c1 = b1v[col + 1];
            float v0 = accB[mi][ni][0] + c0;
            float v1 = accB[mi][ni][1] + c1;
            float v2 = accB[mi][ni][2] + c0;
            float v3 = accB[mi][ni][3] + c1;
            v0 = (v0 > 0.f) ? v0 : 0.01f * v0;
            v1 = (v1 > 0.f) ? v1 : 0.01f * v1;
            v2 = (v2 > 0.f) ? v2 : 0.01f * v2;
            v3 = (v3 > 0.f) ? v3 : 0.01f * v3;
            *reinterpret_cast<__half2*>(&h2s[r0 * 264 + col]) =
                __floats2half2_rn(v0, v1);
            *reinterpret_cast<__half2*>(&h2s[(r0 + 8) * 264 + col]) =
                __floats2half2_rn(v2, v3);
        }
    }
    #pragma unroll
    for (int it = 0; it < 2; it++) {
        int f = it * 512 + tid;               // 1024 float4 chunks of W2
        int crow = f >> 6;
        int k = (f & 63) * 4;
        float4 v = reinterpret_cast<const float4*>(W2)[f];
        *reinterpret_cast<__half2*>(&w2s[crow * 264 + k]) =
            __floats2half2_rn(v.x, v.y);
        *reinterpret_cast<__half2*>(&w2s[crow * 264 + k + 2]) =
            __floats2half2_rn(v.z, v.w);
    }
    __syncthreads();

    // ---------------- Phase C: head (warps 0..7) ----------------------------
    if (warp < 8) {
        float ao[2][4];
        #pragma unroll
        for (int ni = 0; ni < 2; ni++)
            #pragma unroll
            for (int c = 0; c < 4; c++) ao[ni][c] = 0.0f;

        const uint32_t wbb = sbase + 67584;
        const int arow = warp * 16 + (lane & 15);
        const int ahalf = (lane >> 4) * 8;
        const int brow = ((lane >> 4) & 1) * 8 + (lane & 7);
        const int bhalf = ((lane >> 3) & 1) * 8;
        #pragma unroll
        for (int ks = 0; ks < 16; ks++) {
            const int kk = ks * 16;
            uint32_t af[4];
            ldsm_x4(af[0], af[1], af[2], af[3],
                    sbase + (uint32_t)(arow * 264 + kk + ahalf) * 2);
            uint32_t r0, r1, r2, r3;
            ldsm_x4(r0, r1, r2, r3,
                    wbb + (uint32_t)(brow * 264 + kk + bhalf) * 2);
            uint32_t bf0[2] = {r0, r1}, bf1[2] = {r2, r3};
            mma_f16(ao[0], af, bf0);
            mma_f16(ao[1], af, bf1);
        }
        const int m = m0 + warp * 16 + g;
        #pragma unroll
        for (int ni = 0; ni < 2; ni++) {
            const int col = ni * 8 + tg * 2;
            const float c0 = b2v[col], c1 = b2v[col + 1];
            float s0 = 1.0f / (1.0f + expf(-(ao[ni][0] + c0)));
            float s1 = 1.0f / (1.0f + expf(-(ao[ni][1] + c1)));
            float s2 = 1.0f / (1.0f + expf(-(ao[ni][2] + c0)));
            float s3 = 1.0f / (1.0f + expf(-(ao[ni][3] + c1)));
            *reinterpret_cast<float2*>(out + (size_t)m * NCLS + col) =
                make_float2(s0, s1);
            *reinterpret_cast<float2*>(out + (size_t)(m + 8) * NCLS + col) =
                make_float2(s2, s3);
        }
    }
}

// ============================================================================
// Edge bucketing + segmented max (unchanged)
// ============================================================================
__global__ void hist_kernel(const int* __restrict__ dst, int* __restrict__ hist, int E)
{
    int i = blockIdx.x * blockDim.x + threadIdx.x;
    if (i < E) atomicAdd(&hist[dst[i]], 1);
}

__global__ void __launch_bounds__(1024) scan_kernel(
    const int* __restrict__ hist, int* __restrict__ offs,
    int* __restrict__ cursor, int N)
{
    __shared__ int part[1024];
    const int tid = threadIdx.x;
    const int per = N / 1024;
    const int base = tid * per;
    int s = 0;
    for (int i = 0; i < per; i++) s += hist[base + i];
    part[tid] = s;
    __syncthreads();
    for (int d = 1; d < 1024; d <<= 1) {
        int v = (tid >= d) ? part[tid - d] : 0;
        __syncthreads();
        part[tid] += v;
        __syncthreads();
    }
    int run = (tid == 0) ? 0 : part[tid - 1];
    for (int i = 0; i < per; i++) {
        offs[base + i] = run;
        cursor[base + i] = run;
        run += hist[base + i];
    }
    if (tid == 1023) offs[N] = run;
}

__global__ void scatter_edges(const int* __restrict__ src, const int* __restrict__ dst,
                              int* __restrict__ cursor, int* __restrict__ ssrc, int E)
{
    int i = blockIdx.x * blockDim.x + threadIdx.x;
    if (i < E) {
        int p = atomicAdd(&cursor[dst[i]], 1);
        ssrc[p] = src[i];
    }
}

__global__ void __launch_bounds__(256) pool_max(
    const uint2* __restrict__ y, const int* __restrict__ offs,
    const int* __restrict__ ssrc, uint2* __restrict__ pooled, int N)
{
    int w = (blockIdx.x * blockDim.x + threadIdx.x) >> 5;
    int lane = threadIdx.x & 31;
    if (w >= N) return;
    int e = offs[w], end = offs[w + 1];
    __half2 m0 = __float2half2_rn(0.f);
    __half2 m1 = m0;
    for (; e + 7 < end; e += 8) {
        uint2 v[8];
        #pragma unroll
        for (int j = 0; j < 8; j++)
            v[j] = y[(size_t)ssrc[e + j] * 32 + lane];
        #pragma unroll
        for (int j = 0; j < 8; j++) {
            m0 = __hmax2(m0, *(__half2*)&v[j].x);
            m1 = __hmax2(m1, *(__half2*)&v[j].y);
        }
    }
    for (; e < end; e++) {
        uint2 v0 = y[(size_t)ssrc[e] * 32 + lane];
        m0 = __hmax2(m0, *(__half2*)&v0.x);
        m1 = __hmax2(m1, *(__half2*)&v0.y);
    }
    uint2 o;
    o.x = *(uint32_t*)&m0;
    o.y = *(uint32_t*)&m1;
    pooled[(size_t)w * 32 + lane] = o;
}

extern "C" void kernel_launch(void* const* d_in, const int* in_sizes, int n_in,
                              void* d_out, int out_size)
{
    const float* x  = (const float*)d_in[0];
    const float* Wp = (const float*)d_in[1];
    const float* bp = (const float*)d_in[2];
    const float* Ws = (const float*)d_in[3];
    const float* Wn = (const float*)d_in[4];
    const float* bn = (const float*)d_in[5];
    const float* W1 = (const float*)d_in[6];
    const float* b1 = (const float*)d_in[7];
    const float* W2 = (const float*)d_in[8];
    const float* b2 = (const float*)d_in[9];
    const int* src  = (const int*)d_in[10];
    const int* dst  = (const int*)d_in[11];
    float* out = (float*)d_out;

    const int M = in_sizes[0] / H1;   // IN_FEATS == H1 == 128
    const int E = in_sizes[10];

    __half *xh, *y, *pooled, *wph, *wsh, *wnh, *w1h;
    int *hist, *offs, *cursor, *ssrc;
    cudaGetSymbolAddress((void**)&xh, g_xh);
    cudaGetSymbolAddress((void**)&y, g_y);
    cudaGetSymbolAddress((void**)&pooled, g_pooled);
    cudaGetSymbolAddress((void**)&wph, g_wph);
    cudaGetSymbolAddress((void**)&wsh, g_wsh);
    cudaGetSymbolAddress((void**)&wnh, g_wnh);
    cudaGetSymbolAddress((void**)&w1h, g_w1h);
    cudaGetSymbolAddress((void**)&hist, g_hist);
    cudaGetSymbolAddress((void**)&offs, g_offs);
    cudaGetSymbolAddress((void**)&cursor, g_cursor);
    cudaGetSymbolAddress((void**)&ssrc, g_ssrc);

    cudaFuncSetAttribute(gemm_h<ACT_RELU, 1>,
                         cudaFuncAttributeMaxDynamicSharedMemorySize, 65536);
    cudaFuncSetAttribute(fused_tail,
                         cudaFuncAttributeMaxDynamicSharedMemorySize, 102400);

    static cudaStream_t s1 = nullptr;
    static cudaEvent_t evR = nullptr, evS = nullptr;
    if (s1 == nullptr) {
        cudaStreamCreateWithFlags(&s1, cudaStreamNonBlocking);
        cudaEventCreateWithFlags(&evR, cudaEventDisableTiming);
        cudaEventCreateWithFlags(&evS, cudaEventDisableTiming);
    }

    // ---- fork: edge bucketing on side stream ----
    cudaEventRecord(evR, 0);
    cudaStreamWaitEvent(s1, evR, 0);
    cudaMemsetAsync(hist, 0, M * sizeof(int), s1);
    hist_kernel<<<(E + 255) / 256, 256, 0, s1>>>(dst, hist, E);
    scan_kernel<<<1, 1024, 0, s1>>>(hist, offs, cursor, M);
    scatter_edges<<<(E + 255) / 256, 256, 0, s1>>>(src, dst, cursor, ssrc, E);
    cudaEventRecord(evS, s1);

    // ---- main: one fused fp16 conversion ----
    int n4x = M * H1 / 4;
    int n4tot = n4x + 20480;
    conv_all<<<(n4tot + 255) / 256, 256>>>(
        (const float4*)x, (const float4*)Wp, (const float4*)Ws,
        (const float4*)Wn, (const float4*)W1,
        (uint2*)xh, (uint2*)wph, (uint2*)wsh, (uint2*)wnh, (uint2*)w1h, n4x);

    // ---- y = relu(x @ Wp^T + bp) ----
    dim3 g1(1, M / 128);
    gemm_h<ACT_RELU, 1><<<g1, 256, 65536>>>(
        xh, wph, nullptr, nullptr, bp, y, M, H1, H1);

    // ---- join, pooled = segmented max ----
    cudaStreamWaitEvent(0, evS, 0);
    pool_max<<<(M + 7) / 8, 256>>>((const uint2*)y, offs, ssrc,
                                   (uint2*)pooled, M);

    // ---- fused tail: h -> h2 -> out, all on-chip ----
    fused_tail<<<M / 128, 512, 102400>>>(
        xh, wsh, pooled, wnh, bn, w1h, b1, W2, b2, out, M);
}

// round 13
// speedup vs baseline: 4.0774x; 1.5678x over previous
#include <cuda_runtime.h>
#include <cuda_fp16.h>
#include <math.h>
#include <stdint.h>

#define H1 128
#define H2 256
#define NCLS 16
#define MAXN 65536
#define MAXE 1048576

// ---- scratch (device globals: allocation-free per harness rules) ----
__device__ __align__(16) __half g_xh[MAXN * H1];      // x in fp16
__device__ __align__(16) __half g_y[MAXN * H1];       // relu(x@Wp^T+bp)
__device__ __align__(16) __half g_wph[H1 * H1];       // fp16 weights
__device__ __align__(16) __half g_wsh[H1 * H1];
__device__ __align__(16) __half g_wnh[H1 * H1];
__device__ __align__(16) __half g_w1h[H2 * H1];
__device__ __align__(16) int g_hist[MAXN];
__device__ __align__(16) int g_offs[MAXN + 4];
__device__ __align__(16) int g_cursor[MAXN];
__device__ __align__(16) int g_ssrc[MAXE];

enum { ACT_RELU = 1, ACT_LEAKY = 2 };

__device__ __forceinline__ void mma_f16(
    float* c, const uint32_t* a, const uint32_t* b)
{
    asm volatile(
        "mma.sync.aligned.m16n8k16.row.col.f32.f16.f16.f32 "
        "{%0,%1,%2,%3}, {%4,%5,%6,%7}, {%8,%9}, {%0,%1,%2,%3};\n"
        : "+f"(c[0]), "+f"(c[1]), "+f"(c[2]), "+f"(c[3])
        : "r"(a[0]), "r"(a[1]), "r"(a[2]), "r"(a[3]),
          "r"(b[0]), "r"(b[1]));
}

__device__ __forceinline__ void ldsm_x4(
    uint32_t& r0, uint32_t& r1, uint32_t& r2, uint32_t& r3, uint32_t addr)
{
    asm volatile(
        "ldmatrix.sync.aligned.m8n8.x4.shared.b16 {%0,%1,%2,%3}, [%4];"
        : "=r"(r0), "=r"(r1), "=r"(r2), "=r"(r3) : "r"(addr));
}

#define CP_ASYNC16(dst, src) \
    asm volatile("cp.async.cg.shared.global [%0], [%1], 16;" \
                 :: "r"(dst), "l"(src))
#define CP_COMMIT() asm volatile("cp.async.commit_group;")

// one fused fp32 -> fp16 conversion: x, Wp, Ws, Wn, W1
__global__ void conv_all(
    const float4* __restrict__ x,  const float4* __restrict__ wp,
    const float4* __restrict__ ws, const float4* __restrict__ wn,
    const float4* __restrict__ w1,
    uint2* __restrict__ xh,  uint2* __restrict__ wph,
    uint2* __restrict__ wsh, uint2* __restrict__ wnh,
    uint2* __restrict__ w1h, int n4x)
{
    int i = blockIdx.x * blockDim.x + threadIdx.x;
    const float4* in;
    uint2* out;
    int j;
    if (i < n4x) { in = x; out = xh; j = i; }
    else {
        j = i - n4x;
        if      (j < 4096)  { in = wp; out = wph; }
        else if (j < 8192)  { in = ws; out = wsh; j -= 4096; }
        else if (j < 12288) { in = wn; out = wnh; j -= 8192; }
        else if (j < 20480) { in = w1; out = w1h; j -= 12288; }
        else return;
    }
    float4 v = in[j];
    __half2 a = __floats2half2_rn(v.x, v.y);
    __half2 b = __floats2half2_rn(v.z, v.w);
    uint2 o;
    o.x = *(uint32_t*)&a;
    o.y = *(uint32_t*)&b;
    out[j] = o;
}

// ============================================================================
// GEMM1: y = relu(x @ Wp^T + bp), fp16 in/out. 256 thr, 64KB dyn smem.
// ============================================================================
template <int ACT, int NPASS>
__global__ void __launch_bounds__(256) gemm_h(
    const __half* __restrict__ A0, const __half* __restrict__ B0,
    const __half* __restrict__ A1, const __half* __restrict__ B1,
    const float* __restrict__ bias, __half* __restrict__ C,
    int M, int N, int K)
{
    extern __shared__ __align__(16) char dsm[];
    const uint32_t sbase = (uint32_t)__cvta_generic_to_shared(dsm);

    const int tid  = threadIdx.x;
    const int lane = tid & 31;
    const int warp = tid >> 5;
    const int wm = (warp & 1) * 64;
    const int wn = (warp >> 1) * 32;
    const int m0 = blockIdx.y * 128;
    const int n0 = blockIdx.x * 128;
    const int g  = lane >> 2;
    const int tg = lane & 3;

    const int KT = K / 64;
    const int T  = NPASS * KT;

    float acc[4][4][4];
    #pragma unroll
    for (int mi = 0; mi < 4; mi++)
        #pragma unroll
        for (int ni = 0; ni < 4; ni++)
            #pragma unroll
            for (int c = 0; c < 4; c++) acc[mi][ni][c] = 0.0f;

    auto load_tile = [&](int t, int buf) {
        int pass = (NPASS == 2) ? (t / KT) : 0;
        int k0 = (t - pass * KT) * 64;
        const __half* Ap = (NPASS == 2 && pass) ? A1 : A0;
        const __half* Bp = (NPASS == 2 && pass) ? B1 : B0;
        uint32_t abase = sbase + buf * 16384;
        uint32_t bbase = sbase + 32768 + buf * 16384;
        #pragma unroll
        for (int it = 0; it < 4; it++) {
            int f = it * 256 + tid;
            int r = f >> 3, c = f & 7;
            uint32_t soff = (uint32_t)(r * 128 + ((c ^ (r & 7)) << 4));
            CP_ASYNC16(abase + soff, Ap + (size_t)(m0 + r) * K + k0 + c * 8);
            CP_ASYNC16(bbase + soff, Bp + (size_t)(n0 + r) * K + k0 + c * 8);
        }
        CP_COMMIT();
    };

    load_tile(0, 0);
    int buf = 0;
    for (int t = 0; t < T; t++) {
        if (t + 1 < T) {
            load_tile(t + 1, buf ^ 1);
            asm volatile("cp.async.wait_group 1;");
        } else {
            asm volatile("cp.async.wait_group 0;");
        }
        __syncthreads();

        uint32_t abase = sbase + buf * 16384;
        uint32_t bbase = sbase + 32768 + buf * 16384;
        #pragma unroll
        for (int ks = 0; ks < 4; ks++) {
            const int kk = ks * 16;
            const int kcA = (kk >> 3) + (lane >> 4);
            const uint32_t aswz = (uint32_t)((kcA ^ (lane & 7)) << 4);
            uint32_t af[4][4];
            #pragma unroll
            for (int mi = 0; mi < 4; mi++)
                ldsm_x4(af[mi][0], af[mi][1], af[mi][2], af[mi][3],
                        abase + (uint32_t)((wm + mi * 16 + (lane & 15)) * 128)
                              + aswz);
            const int kcB = (kk >> 3) + ((lane >> 3) & 1);
            const uint32_t bswz = (uint32_t)((kcB ^ (lane & 7)) << 4);
            const int brow = wn + ((lane >> 4) & 1) * 8 + (lane & 7);
            uint32_t bf[4][2];
            #pragma unroll
            for (int nip = 0; nip < 2; nip++) {
                uint32_t r0, r1, r2, r3;
                ldsm_x4(r0, r1, r2, r3,
                        bbase + (uint32_t)((brow + nip * 16) * 128) + bswz);
                bf[2 * nip][0] = r0;     bf[2 * nip][1] = r1;
                bf[2 * nip + 1][0] = r2; bf[2 * nip + 1][1] = r3;
            }
            #pragma unroll
            for (int mi = 0; mi < 4; mi++)
                #pragma unroll
                for (int ni = 0; ni < 4; ni++)
                    mma_f16(acc[mi][ni], af[mi], bf[ni]);
        }
        __syncthreads();
        buf ^= 1;
    }

    #pragma unroll
    for (int mi = 0; mi < 4; mi++) {
        const int r0 = m0 + wm + mi * 16 + g;
        #pragma unroll
        for (int ni = 0; ni < 4; ni++) {
            const int col = n0 + wn + ni * 8 + tg * 2;
            const float b0 = bias[col], b1 = bias[col + 1];
            float v0 = acc[mi][ni][0] + b0;
            float v1 = acc[mi][ni][1] + b1;
            float v2 = acc[mi][ni][2] + b0;
            float v3 = acc[mi][ni][3] + b1;
            if (ACT == ACT_RELU) {
                v0 = fmaxf(v0, 0.f); v1 = fmaxf(v1, 0.f);
                v2 = fmaxf(v2, 0.f); v3 = fmaxf(v3, 0.f);
            }
            if (ACT == ACT_LEAKY) {
                v0 = (v0 > 0.f) ? v0 : 0.01f * v0;
                v1 = (v1 > 0.f) ? v1 : 0.01f * v1;
                v2 = (v2 > 0.f) ? v2 : 0.01f * v2;
                v3 = (v3 > 0.f) ? v3 : 0.01f * v3;
            }
            *reinterpret_cast<__half2*>(C + (size_t)r0 * N + col) =
                __floats2half2_rn(v0, v1);
            *reinterpret_cast<__half2*>(C + (size_t)(r0 + 8) * N + col) =
                __floats2half2_rn(v2, v3);
        }
    }
}

// ============================================================================
// FUSED TAIL (now includes the pool): per 128-row block, after gemm1:
//   Phase 0: p_s[r] = segmax over bucketed edges of y[src]  -> smem (swizzled)
//   Phase A: h   = leaky(x@Ws^T + p_s@Wn^T + bn)            -> smem h_s
//   Phase B: h2  = leaky(h_s@W1^T + b1)                     -> smem h2s
//   Phase C: out = sigmoid(h2s@W2^T + b2)                   -> gmem fp32
// 512 threads = 16 warps, 1 CTA/SM (register-bound). Dyn smem 133120 B:
//   [0, 34816)       p_s (128x256B swizzled tile) -> later h_s (stride 272B)
//                    -> later h2s (stride 528B, spills into R1)
//   R1 = 34816       x tile  -> later W1 rows 128..255
//   R2 = 67584       Ws tile -> later W1 rows 0..127 ; later w2s @67584
//   R3 = 100352      Wn tile
// All operand tiles: 128 rows x 256B, 16B chunk c at r*256 + ((c^(r&7))<<4).
// ============================================================================
__global__ void __launch_bounds__(512) fused_tail(
    const __half* __restrict__ X,  const __half* __restrict__ Wsh,
    const __half* __restrict__ Wnh, const float* __restrict__ bn,
    const __half* __restrict__ W1h, const float* __restrict__ b1v,
    const float* __restrict__ W2,  const float* __restrict__ b2v,
    const uint2* __restrict__ Y,   const int* __restrict__ offs,
    const int* __restrict__ ssrc,  float* __restrict__ out, int M)
{
    extern __shared__ __align__(16) char dsm[];
    const uint32_t sbase = (uint32_t)__cvta_generic_to_shared(dsm);
    const int R1 = 34816, R2 = 67584, R3 = 100352;
    const int K = 128;

    const int tid  = threadIdx.x;
    const int lane = tid & 31;
    const int warp = tid >> 5;
    const int m0 = blockIdx.x * 128;
    const int g  = lane >> 2;
    const int tg = lane & 3;

    // stage a 128x128 fp16 tile (256B rows, swizzled) via cp.async
    auto stage128 = [&](uint32_t base, const __half* G) {
        #pragma unroll
        for (int it = 0; it < 4; it++) {
            int f = it * 512 + tid;
            int r = f >> 4, c = f & 15;
            uint32_t soff = (uint32_t)(r * 256 + ((c ^ (r & 7)) << 4));
            CP_ASYNC16(base + soff, G + (size_t)r * K + c * 8);
        }
    };

    stage128(sbase + R1, X + (size_t)m0 * K);
    stage128(sbase + R2, Wsh);
    stage128(sbase + R3, Wnh);
    CP_COMMIT();

    // ---- Phase 0: gather segmented max into p_s (overlaps cp.async) ----
    {
        const __half2 z = __float2half2_rn(0.f);
        for (int i = 0; i < 8; i++) {
            int r = warp * 8 + i;
            int n = m0 + r;
            int e = offs[n], end = offs[n + 1];
            __half2 a = z, b = z;
            for (; e + 3 < end; e += 4) {
                uint2 v0 = Y[(size_t)ssrc[e]     * 32 + lane];
                uint2 v1 = Y[(size_t)ssrc[e + 1] * 32 + lane];
                uint2 v2 = Y[(size_t)ssrc[e + 2] * 32 + lane];
                uint2 v3 = Y[(size_t)ssrc[e + 3] * 32 + lane];
                a = __hmax2(a, __hmax2(
                        __hmax2(*(__half2*)&v0.x, *(__half2*)&v1.x),
                        __hmax2(*(__half2*)&v2.x, *(__half2*)&v3.x)));
                b = __hmax2(b, __hmax2(
                        __hmax2(*(__half2*)&v0.y, *(__half2*)&v1.y),
                        __hmax2(*(__half2*)&v2.y, *(__half2*)&v3.y)));
            }
            for (; e < end; e++) {
                uint2 v0 = Y[(size_t)ssrc[e] * 32 + lane];
                a = __hmax2(a, *(__half2*)&v0.x);
                b = __hmax2(b, *(__half2*)&v0.y);
            }
            // lane owns cols [4*lane, 4*lane+4): chunk lane/2, sub (lane&1)*8B
            uint32_t off = (uint32_t)(r * 256 + (((lane >> 1) ^ (r & 7)) << 4)
                                      + (lane & 1) * 8);
            uint2 o;
            o.x = *(uint32_t*)&a;
            o.y = *(uint32_t*)&b;
            *reinterpret_cast<uint2*>(dsm + off) = o;
        }
    }
    asm volatile("cp.async.wait_group 0;");
    __syncthreads();

    // ---- Phase A: 16 warps (4M x 4N), 32x32 per warp, two passes ----
    const int wmA = (warp & 3) * 32;
    const int wnA = (warp >> 2) * 32;

    float acc[2][4][4];
    #pragma unroll
    for (int mi = 0; mi < 2; mi++)
        #pragma unroll
        for (int ni = 0; ni < 4; ni++)
            #pragma unroll
            for (int c = 0; c < 4; c++) acc[mi][ni][c] = 0.0f;

    auto do_pass = [&](uint32_t abase, uint32_t bbase) {
        #pragma unroll
        for (int ks = 0; ks < 8; ks++) {
            const int kk = ks * 16;
            const int kcA = (kk >> 3) + (lane >> 4);
            const uint32_t aswz = (uint32_t)((kcA ^ (lane & 7)) << 4);
            uint32_t af[2][4];
            #pragma unroll
            for (int mi = 0; mi < 2; mi++)
                ldsm_x4(af[mi][0], af[mi][1], af[mi][2], af[mi][3],
                        abase + (uint32_t)((wmA + mi * 16 + (lane & 15)) * 256)
                              + aswz);
            const int kcB = (kk >> 3) + ((lane >> 3) & 1);
            const uint32_t bswz = (uint32_t)((kcB ^ (lane & 7)) << 4);
            const int brow = wnA + ((lane >> 4) & 1) * 8 + (lane & 7);
            uint32_t bf[4][2];
            #pragma unroll
            for (int nip = 0; nip < 2; nip++) {
                uint32_t r0, r1, r2, r3;
                ldsm_x4(r0, r1, r2, r3,
                        bbase + (uint32_t)((brow + nip * 16) * 256) + bswz);
                bf[2 * nip][0] = r0;     bf[2 * nip][1] = r1;
                bf[2 * nip + 1][0] = r2; bf[2 * nip + 1][1] = r3;
            }
            #pragma unroll
            for (int mi = 0; mi < 2; mi++)
                #pragma unroll
                for (int ni = 0; ni < 4; ni++)
                    mma_f16(acc[mi][ni], af[mi], bf[ni]);
        }
    };

    do_pass(sbase + R1, sbase + R2);      // x @ Ws^T
    __syncthreads();                      // R1/R2 reads done everywhere
    stage128(sbase + R2, W1h);            // W1 rows 0..127
    stage128(sbase + R1, W1h + 128 * K);  // W1 rows 128..255
    CP_COMMIT();
    do_pass(sbase + 0, sbase + R3);       // pooled @ Wn^T
    __syncthreads();                      // p_s reads done before h_s writes

    // epilogue A -> h_s (stride 136 halfs = 272B, base 0)
    __half* h_s = reinterpret_cast<__half*>(dsm);
    #pragma unroll
    for (int mi = 0; mi < 2; mi++) {
        const int r0 = wmA + mi * 16 + g;
        #pragma unroll
        for (int ni = 0; ni < 4; ni++) {
            const int col = wnA + ni * 8 + tg * 2;
            const float c0 = bn[col], c1 = bn[col + 1];
            float v0 = acc[mi][ni][0] + c0;
            float v1 = acc[mi][ni][1] + c1;
            float v2 = acc[mi][ni][2] + c0;
            float v3 = acc[mi][ni][3] + c1;
            v0 = (v0 > 0.f) ? v0 : 0.01f * v0;
            v1 = (v1 > 0.f) ? v1 : 0.01f * v1;
            v2 = (v2 > 0.f) ? v2 : 0.01f * v2;
            v3 = (v3 > 0.f) ? v3 : 0.01f * v3;
            *reinterpret_cast<__half2*>(&h_s[r0 * 136 + col]) =
                __floats2half2_rn(v0, v1);
            *reinterpret_cast<__half2*>(&h_s[(r0 + 8) * 136 + col]) =
                __floats2half2_rn(v2, v3);
        }
    }
    asm volatile("cp.async.wait_group 0;");
    __syncthreads();

    // ---- Phase B: h2 = leaky(h_s @ W1^T + b1), 16 warps (2M x 8N) ----
    const int wmB = (warp & 1) * 64;
    const int wnB = (warp >> 1) * 32;
    const uint32_t w1base = (wnB < 128) ? (sbase + R2) : (sbase + R1);
    const int wrow0 = (wnB < 128) ? wnB : (wnB - 128);

    float accB[4][4][4];
    #pragma unroll
    for (int mi = 0; mi < 4; mi++)
        #pragma unroll
        for (int ni = 0; ni < 4; ni++)
            #pragma unroll
            for (int c = 0; c < 4; c++) accB[mi][ni][c] = 0.0f;

    #pragma unroll
    for (int ks = 0; ks < 8; ks++) {
        const int kk = ks * 16;
        uint32_t af[4][4];
        #pragma unroll
        for (int mi = 0; mi < 4; mi++) {
            int arow = wmB + mi * 16 + (lane & 15);
            uint32_t addr = sbase +
                (uint32_t)(arow * 136 + kk + (lane >> 4) * 8) * 2;
            ldsm_x4(af[mi][0], af[mi][1], af[mi][2], af[mi][3], addr);
        }
        const int kcB = (kk >> 3) + ((lane >> 3) & 1);
        const uint32_t bswz = (uint32_t)((kcB ^ (lane & 7)) << 4);
        const int brow = wrow0 + ((lane >> 4) & 1) * 8 + (lane & 7);
        uint32_t bf[4][2];
        #pragma unroll
        for (int nip = 0; nip < 2; nip++) {
            uint32_t r0, r1, r2, r3;
            ldsm_x4(r0, r1, r2, r3,
                    w1base + (uint32_t)((brow + nip * 16) * 256) + bswz);
            bf[2 * nip][0] = r0;     bf[2 * nip][1] = r1;
            bf[2 * nip + 1][0] = r2; bf[2 * nip + 1][1] = r3;
        }
        #pragma unroll
        for (int mi = 0; mi < 4; mi++)
            #pragma unroll
            for (int ni = 0; ni < 4; ni++)
                mma_f16(accB[mi][ni], af[mi], bf[ni]);
    }
    __syncthreads();   // h_s & W1 reads done; safe to overwrite with h2s/w2s

    __half* h2s = reinterpret_cast<__half*>(dsm);
    __half* w2s = h2s + 128 * 264;        // byte offset 67584
    #pragma unroll
    for (int mi = 0; mi < 4; mi++) {
        const int r0 = wmB + mi * 16 + g;
        #pragma unroll
        for (int ni = 0; ni < 4; ni++) {
            const int col = wnB + ni * 8 + tg * 2;
            const float c0 = b1v[col], c1 = b1v[col + 1];
            float v0 = accB[mi][ni][0] + c0;
            float v1 = accB[mi][ni][1] + c1;
            float v2 = accB[mi][ni][2] + c0;
            float v3 = accB[mi][ni][3] + c1;
            v0 = (v0 > 0.f) ? v0 : 0.01f * v0;
            v1 = (v1 > 0.f) ? v1 : 0.01f * v1;
            v2 = (v2 > 0.f) ? v2 : 0.01f * v2;
            v3 = (v3 > 0.f) ? v3 : 0.01f * v3;
            *reinterpret_cast<__half2*>(&h2s[r0 * 264 + col]) =
                __floats2half2_rn(v0, v1);
            *reinterpret_cast<__half2*>(&h2s[(r0 + 8) * 264 + col]) =
                __floats2half2_rn(v2, v3);
        }
    }
    #pragma unroll
    for (int it = 0; it < 2; it++) {
        int f = it * 512 + tid;               // 1024 float4 chunks of W2
        int crow = f >> 6;
        int k = (f & 63) * 4;
        float4 v = reinterpret_cast<const float4*>(W2)[f];
        *reinterpret_cast<__half2*>(&w2s[crow * 264 + k]) =
            __floats2half2_rn(v.x, v.y);
        *reinterpret_cast<__half2*>(&w2s[crow * 264 + k + 2]) =
            __floats2half2_rn(v.z, v.w);
    }
    __syncthreads();

    // ---- Phase C: head (warps 0..7) ----
    if (warp < 8) {
        float ao[2][4];
        #pragma unroll
        for (int ni = 0; ni < 2; ni++)
            #pragma unroll
            for (int c = 0; c < 4; c++) ao[ni][c] = 0.0f;

        const uint32_t wbb = sbase + 67584;
        const int arow = warp * 16 + (lane & 15);
        const int ahalf = (lane >> 4) * 8;
        const int brow = ((lane >> 4) & 1) * 8 + (lane & 7);
        const int bhalf = ((lane >> 3) & 1) * 8;
        #pragma unroll
        for (int ks = 0; ks < 16; ks++) {
            const int kk = ks * 16;
            uint32_t af[4];
            ldsm_x4(af[0], af[1], af[2], af[3],
                    sbase + (uint32_t)(arow * 264 + kk + ahalf) * 2);
            uint32_t r0, r1, r2, r3;
            ldsm_x4(r0, r1, r2, r3,
                    wbb + (uint32_t)(brow * 264 + kk + bhalf) * 2);
            uint32_t bf0[2] = {r0, r1}, bf1[2] = {r2, r3};
            mma_f16(ao[0], af, bf0);
            mma_f16(ao[1], af, bf1);
        }
        const int m = m0 + warp * 16 + g;
        #pragma unroll
        for (int ni = 0; ni < 2; ni++) {
            const int col = ni * 8 + tg * 2;
            const float c0 = b2v[col], c1 = b2v[col + 1];
            float s0 = 1.0f / (1.0f + expf(-(ao[ni][0] + c0)));
            float s1 = 1.0f / (1.0f + expf(-(ao[ni][1] + c1)));
            float s2 = 1.0f / (1.0f + expf(-(ao[ni][2] + c0)));
            float s3 = 1.0f / (1.0f + expf(-(ao[ni][3] + c1)));
            *reinterpret_cast<float2*>(out + (size_t)m * NCLS + col) =
                make_float2(s0, s1);
            *reinterpret_cast<float2*>(out + (size_t)(m + 8) * NCLS + col) =
                make_float2(s2, s3);
        }
    }
}

// ============================================================================
// Edge bucketing: int4-vectorized hist/scatter, int4 single-block scan
// ============================================================================
__global__ void hist_kernel(const int4* __restrict__ dst4,
                            int* __restrict__ hist, int E4)
{
    int i = blockIdx.x * blockDim.x + threadIdx.x;
    if (i < E4) {
        int4 d = dst4[i];
        atomicAdd(&hist[d.x], 1);
        atomicAdd(&hist[d.y], 1);
        atomicAdd(&hist[d.z], 1);
        atomicAdd(&hist[d.w], 1);
    }
}

__global__ void __launch_bounds__(1024) scan_kernel(
    const int4* __restrict__ h4, int* __restrict__ offs,
    int* __restrict__ cursor, int N)
{
    __shared__ int part[1024];
    const int tid = threadIdx.x;
    int s = 0;
    #pragma unroll 4
    for (int i = 0; i < 16; i++) {
        int4 h = h4[tid * 16 + i];
        s += h.x + h.y + h.z + h.w;
    }
    part[tid] = s;
    __syncthreads();
    for (int d = 1; d < 1024; d <<= 1) {
        int v = (tid >= d) ? part[tid - d] : 0;
        __syncthreads();
        part[tid] += v;
        __syncthreads();
    }
    int run = (tid == 0) ? 0 : part[tid - 1];
    #pragma unroll 4
    for (int i = 0; i < 16; i++) {
        int4 h = h4[tid * 16 + i];
        int4 o;
        o.x = run;
        o.y = o.x + h.x;
        o.z = o.y + h.y;
        o.w = o.z + h.z;
        run = o.w + h.w;
        reinterpret_cast<int4*>(offs)[tid * 16 + i] = o;
        reinterpret_cast<int4*>(cursor)[tid * 16 + i] = o;
    }
    if (tid == 1023) offs[N] = run;
}

__global__ void scatter_edges(const int4* __restrict__ src4,
                              const int4* __restrict__ dst4,
                              int* __restrict__ cursor,
                              int* __restrict__ ssrc, int E4)
{
    int i = blockIdx.x * blockDim.x + threadIdx.x;
    if (i < E4) {
        int4 s = src4[i];
        int4 d = dst4[i];
        ssrc[atomicAdd(&cursor[d.x], 1)] = s.x;
        ssrc[atomicAdd(&cursor[d.y], 1)] = s.y;
        ssrc[atomicAdd(&cursor[d.z], 1)] = s.z;
        ssrc[atomicAdd(&cursor[d.w], 1)] = s.w;
    }
}

extern "C" void kernel_launch(void* const* d_in, const int* in_sizes, int n_in,
                              void* d_out, int out_size)
{
    const float* x  = (const float*)d_in[0];
    const float* Wp = (const float*)d_in[1];
    const float* bp = (const float*)d_in[2];
    const float* Ws = (const float*)d_in[3];
    const float* Wn = (const float*)d_in[4];
    const float* bn = (const float*)d_in[5];
    const float* W1 = (const float*)d_in[6];
    const float* b1 = (const float*)d_in[7];
    const float* W2 = (const float*)d_in[8];
    const float* b2 = (const float*)d_in[9];
    const int* src  = (const int*)d_in[10];
    const int* dst  = (const int*)d_in[11];
    float* out = (float*)d_out;

    const int M = in_sizes[0] / H1;   // IN_FEATS == H1 == 128
    const int E = in_sizes[10];
    const int E4 = E / 4;

    __half *xh, *y, *wph, *wsh, *wnh, *w1h;
    int *hist, *offs, *cursor, *ssrc;
    cudaGetSymbolAddress((void**)&xh, g_xh);
    cudaGetSymbolAddress((void**)&y, g_y);
    cudaGetSymbolAddress((void**)&wph, g_wph);
    cudaGetSymbolAddress((void**)&wsh, g_wsh);
    cudaGetSymbolAddress((void**)&wnh, g_wnh);
    cudaGetSymbolAddress((void**)&w1h, g_w1h);
    cudaGetSymbolAddress((void**)&hist, g_hist);
    cudaGetSymbolAddress((void**)&offs, g_offs);
    cudaGetSymbolAddress((void**)&cursor, g_cursor);
    cudaGetSymbolAddress((void**)&ssrc, g_ssrc);

    cudaFuncSetAttribute(gemm_h<ACT_RELU, 1>,
                         cudaFuncAttributeMaxDynamicSharedMemorySize, 65536);
    cudaFuncSetAttribute(fused_tail,
                         cudaFuncAttributeMaxDynamicSharedMemorySize, 133120);

    static cudaStream_t s1 = nullptr;
    static cudaEvent_t evR = nullptr, evS = nullptr;
    if (s1 == nullptr) {
        cudaStreamCreateWithFlags(&s1, cudaStreamNonBlocking);
        cudaEventCreateWithFlags(&evR, cudaEventDisableTiming);
        cudaEventCreateWithFlags(&evS, cudaEventDisableTiming);
    }

    // ---- fork: edge bucketing on side stream ----
    cudaEventRecord(evR, 0);
    cudaStreamWaitEvent(s1, evR, 0);
    cudaMemsetAsync(hist, 0, M * sizeof(int), s1);
    hist_kernel<<<(E4 + 255) / 256, 256, 0, s1>>>((const int4*)dst, hist, E4);
    scan_kernel<<<1, 1024, 0, s1>>>((const int4*)hist, offs, cursor, M);
    scatter_edges<<<(E4 + 255) / 256, 256, 0, s1>>>(
        (const int4*)src, (const int4*)dst, cursor, ssrc, E4);
    cudaEventRecord(evS, s1);

    // ---- main: one fused fp16 conversion ----
    int n4x = M * H1 / 4;
    int n4tot = n4x + 20480;
    conv_all<<<(n4tot + 255) / 256, 256>>>(
        (const float4*)x, (const float4*)Wp, (const float4*)Ws,
        (const float4*)Wn, (const float4*)W1,
        (uint2*)xh, (uint2*)wph, (uint2*)wsh, (uint2*)wnh, (uint2*)w1h, n4x);

    // ---- y = relu(x @ Wp^T + bp) ----
    dim3 g1(1, M / 128);
    gemm_h<ACT_RELU, 1><<<g1, 256, 65536>>>(
        xh, wph, nullptr, nullptr, bp, y, M, H1, H1);

    // ---- join bucketing, then the whole rest fused ----
    cudaStreamWaitEvent(0, evS, 0);
    fused_tail<<<M / 128, 512, 133120>>>(
        xh, wsh, wnh, bn, w1h, b1, W2, b2,
        (const uint2*)y, offs, ssrc, out, M);
}